// round 15
// baseline (speedup 1.0000x reference)
#include <cuda_runtime.h>
#include <math.h>

#define BATCH 8
#define C 256
#define NH 4
#define HD 64
#define P 1024
#define KF 256
#define HW 4096
#define PLANE32 1024

__device__ float g_xd[BATCH*C*PLANE32];
__device__ float g_qkv[BATCH*NH*P*192];
__device__ float g_outc[BATCH*C*PLANE32];
__device__ float g_coarse[BATCH*C*HW];
__device__ float g_sm[32*1024], g_ssi[32*1024];
__device__ float g_part[32*16*1024];
__device__ int   g_topk[32*KF];
__device__ float g_y[BATCH*C*HW];
__device__ float g_yd[BATCH*C*HW];
__device__ unsigned g_wdh[256*2048], g_wdl[256*2048];
__device__ unsigned g_wuh[4*256*512], g_wul[4*256*512];
__device__ unsigned g_pwh[256*128],  g_pwl[256*128];

// ---- bf16 helpers ----
__device__ __forceinline__ unsigned bpack(float x0, float x1){
    unsigned r; asm("cvt.rn.bf16x2.f32 %0, %1, %2;" : "=r"(r) : "f"(x1), "f"(x0)); return r;
}
__device__ __forceinline__ void bsplit2(float x0, float x1, unsigned &h, unsigned &l){
    h = bpack(x0, x1);
    l = bpack(x0 - __uint_as_float(h << 16), x1 - __uint_as_float(h & 0xFFFF0000u));
}
__device__ __forceinline__ void bmma(float* c, unsigned a0,unsigned a1,unsigned a2,unsigned a3,
                                     unsigned b0,unsigned b1){
    asm volatile("mma.sync.aligned.m16n8k16.row.col.f32.bf16.bf16.f32 "
        "{%0,%1,%2,%3}, {%4,%5,%6,%7}, {%8,%9}, {%0,%1,%2,%3};"
        : "+f"(c[0]),"+f"(c[1]),"+f"(c[2]),"+f"(c[3])
        : "r"(a0),"r"(a1),"r"(a2),"r"(a3),"r"(b0),"r"(b1));
}
__device__ __forceinline__ void bmma3(float* c, const unsigned* Ah, const unsigned* Al,
                                      const unsigned* Bh, const unsigned* Bl){
    bmma(c, Ah[0],Ah[1],Ah[2],Ah[3], Bh[0],Bh[1]);
    bmma(c, Ah[0],Ah[1],Ah[2],Ah[3], Bl[0],Bl[1]);
    bmma(c, Al[0],Al[1],Al[2],Al[3], Bh[0],Bh[1]);
}
__device__ __forceinline__ void ldsm4(unsigned &r0, unsigned &r1, unsigned &r2, unsigned &r3,
                                      const unsigned* p){
    unsigned a = (unsigned)__cvta_generic_to_shared(p);
    asm volatile("ldmatrix.sync.aligned.m8n8.x4.shared.b16 {%0,%1,%2,%3}, [%4];"
        : "=r"(r0),"=r"(r1),"=r"(r2),"=r"(r3) : "r"(a));
}
__device__ __forceinline__ void ldsm2(unsigned &r0, unsigned &r1, const unsigned* p){
    unsigned a = (unsigned)__cvta_generic_to_shared(p);
    asm volatile("ldmatrix.sync.aligned.m8n8.x2.shared.b16 {%0,%1}, [%2];"
        : "=r"(r0),"=r"(r1) : "r"(a));
}
#define AOFF(lane,s) (((lane)&15)*(s) + (((lane)>>4)<<2))
#define BOFF(lane,s) (((((lane)>>4)<<3)+((lane)&7))*(s) + ((((lane)>>3)&1)<<2))
#define B2OFF(lane,s) ((((lane)&7))*(s) + ((((lane)>>3)&1)<<2))

// ---- weight prep ----
__global__ __launch_bounds__(256) void k_prep_wd(const float* __restrict__ w){
    int i = blockIdx.x*256 + threadIdx.x;
    float2 v = *(const float2*)(w + 2*(size_t)i);
    bsplit2(v.x, v.y, g_wdh[i], g_wdl[i]);
}
__global__ __launch_bounds__(256) void k_wt(const float* __restrict__ wup){
    int idx = blockIdx.x*256 + threadIdx.x;
    int cls = idx>>17, co = (idx>>9)&255, kp = idx&511;
    int py = cls>>1, pxp = cls&1;
    int ci = kp>>1, j0 = (kp&1)*2;
    int ky0 = py + ((j0>>1)<<1);
    float v0 = wup[((size_t)ci*256+co)*16 + ky0*4 + pxp];
    float v1 = wup[((size_t)ci*256+co)*16 + ky0*4 + pxp + 2];
    bsplit2(v0, v1, g_wuh[idx], g_wul[idx]);
}
__global__ __launch_bounds__(256) void k_prep_pw(const float* __restrict__ w){
    int i = blockIdx.x*256 + threadIdx.x;
    float2 v = *(const float2*)(w + 2*(size_t)i);
    bsplit2(v.x, v.y, g_pwh[i], g_pwl[i]);
}

// ---- down conv bf16 (round-12 frozen): grid(128,4), warp m32 x n16 ----
__global__ __launch_bounds__(256) void k_down_t(const float* __restrict__ x,
                                                const float* __restrict__ bias){
    int b = blockIdx.x>>4, oyp = blockIdx.x&15;
    int co0 = blockIdx.y*64;
    __shared__ unsigned sWh[64*36], sWl[64*36];
    __shared__ float sraw[4*6*72];
    int t=threadIdx.x, w=t>>5, lane=t&31, gp=lane>>2, tig=lane&3;
    int mrow=(w>>2)*32, ncol=(w&3)*16;
    int aoff = AOFF(lane,36);
    float c[2][2][4];
#pragma unroll
    for (int i=0;i<2;i++)
#pragma unroll
    for (int jn=0;jn<2;jn++)
#pragma unroll
    for (int k=0;k<4;k++) c[i][jn][k]=0.f;
    for (int cc=0; cc<64; cc++){
        __syncthreads();
        for (int idx=t; idx<512; idx+=256){
            int co=idx>>3, c4=(idx&7)<<2;
            *(uint4*)(sWh + co*36 + c4) = *(const uint4*)(g_wdh + (size_t)(co0+co)*2048 + cc*32 + c4);
            *(uint4*)(sWl + co*36 + c4) = *(const uint4*)(g_wdl + (size_t)(co0+co)*2048 + cc*32 + c4);
        }
        int ci0 = cc*4;
        for (int idx=t; idx<384; idx+=256){
            int rowid = idx>>4, c4=(idx&15)<<2;
            int ci4 = rowid/6, r = rowid - ci4*6;
            int iy = oyp*4 - 1 + r;
            float4 v = make_float4(0.f,0.f,0.f,0.f);
            if (iy>=0 && iy<64)
                v = *(const float4*)(x + (((size_t)(b*C + ci0+ci4))<<12) + (iy<<6) + c4);
            *(float4*)(sraw + rowid*72 + 4 + c4) = v;
        }
        if (t<24){ sraw[t*72+3]=0.f; sraw[t*72+68]=0.f; }
        __syncthreads();
#pragma unroll
        for (int kk=0;kk<4;kk++){
            unsigned Ah[2][4], Al[2][4], Bh[2][2], Bl[2][2];
#pragma unroll
            for (int mi=0;mi<2;mi++){
                ldsm4(Ah[mi][0],Ah[mi][1],Ah[mi][2],Ah[mi][3],
                      sWh + (mrow+mi*16)*36 + kk*8 + aoff);
                ldsm4(Al[mi][0],Al[mi][1],Al[mi][2],Al[mi][3],
                      sWl + (mrow+mi*16)*36 + kk*8 + aoff);
            }
#pragma unroll
            for (int ni=0;ni<2;ni++){
                int n = ncol+ni*8+gp; int opy=n>>5, opx=n&31;
#pragma unroll
                for (int kj=0;kj<2;kj++){
                    int k0 = kk*16 + kj*8 + 2*tig;
                    int ci4=k0>>4, tap=k0&15, ky=tap>>2, kx=tap&3;
                    const float* pr = sraw + (ci4*6 + 2*opy+ky)*72 + 3 + 2*opx + kx;
                    bsplit2(pr[0], pr[1], Bh[ni][kj], Bl[ni][kj]);
                }
            }
#pragma unroll
            for (int mi=0;mi<2;mi++)
#pragma unroll
            for (int ni=0;ni<2;ni++)
                bmma3(c[mi][ni], Ah[mi], Al[mi], Bh[ni], Bl[ni]);
        }
    }
#pragma unroll
    for (int mi=0;mi<2;mi++){
        int co = co0+mrow+mi*16+gp;
        float b0v = bias[co], b1v = bias[co+8];
#pragma unroll
        for (int ni=0;ni<2;ni++){
            int n = ncol+ni*8+2*tig;
            size_t o = ((size_t)(b*C+co)<<10) + oyp*64 + n;
            *(float2*)(g_xd + o) = make_float2(c[mi][ni][0]+b0v, c[mi][ni][1]+b0v);
            *(float2*)(g_xd + o + (8<<10)) = make_float2(c[mi][ni][2]+b1v, c[mi][ni][3]+b1v);
        }
    }
}

// ---- convT bf16: grid(64,16); A via ldmatrix; also writes g_y ----
__global__ __launch_bounds__(256) void k_up_t(const float* __restrict__ bup){
    int b = blockIdx.x>>3, uq = blockIdx.x&7;
    int cls = blockIdx.y>>2, co0 = (blockIdx.y&3)*64;
    int py = cls>>1, pxp = cls&1;
    __shared__ unsigned sWh[64*36], sWl[64*36];
    __shared__ float sraw[16*5*40];
    int t=threadIdx.x, w=t>>5, lane=t&31, gp=lane>>2, tig=lane&3;
    int mrow=(w>>2)*32, ncol=(w&3)*32;
    int aoff = AOFF(lane,36);
    float c[2][4][4];
#pragma unroll
    for (int i=0;i<2;i++)
#pragma unroll
    for (int jn=0;jn<4;jn++)
#pragma unroll
    for (int k=0;k<4;k++) c[i][jn][k]=0.f;
    for (int cc=0; cc<16; cc++){
        __syncthreads();
        for (int idx=t; idx<512; idx+=256){
            int co=idx>>3, c4=(idx&7)<<2;
            size_t s = (size_t)cls*131072 + (size_t)(co0+co)*512 + cc*32 + c4;
            *(uint4*)(sWh + co*36 + c4) = *(const uint4*)(g_wuh + s);
            *(uint4*)(sWl + co*36 + c4) = *(const uint4*)(g_wul + s);
        }
        int ci0 = cc*16;
        for (int idx=t; idx<640; idx+=256){
            int rowid=idx>>3, c4=(idx&7)<<2;
            int ci16=rowid/5, rr=rowid-ci16*5;
            int iy = uq*4 - py + rr;
            float4 v = make_float4(0.f,0.f,0.f,0.f);
            if (iy>=0 && iy<32)
                v = *(const float4*)(g_outc + (((size_t)(b*C+ci0+ci16))<<10) + (iy<<5) + c4);
            *(float4*)(sraw + rowid*40 + 4 + c4) = v;
        }
        if (t<80){ sraw[t*40+3]=0.f; sraw[t*40+36]=0.f; }
        __syncthreads();
#pragma unroll
        for (int kk=0;kk<4;kk++){
            unsigned Ah[2][4], Al[2][4], Bh[4][2], Bl[4][2];
#pragma unroll
            for (int mi=0;mi<2;mi++){
                ldsm4(Ah[mi][0],Ah[mi][1],Ah[mi][2],Ah[mi][3],
                      sWh + (mrow+mi*16)*36 + kk*8 + aoff);
                ldsm4(Al[mi][0],Al[mi][1],Al[mi][2],Al[mi][3],
                      sWl + (mrow+mi*16)*36 + kk*8 + aoff);
            }
#pragma unroll
            for (int ni=0;ni<4;ni++){
                int n = ncol+ni*8+gp; int uu=n>>5, vv=n&31;
#pragma unroll
                for (int kj=0;kj<2;kj++){
                    int k0 = kk*16 + kj*8 + 2*tig;
                    int ci16=k0>>2, j=k0&3;
                    const float* pr = sraw + (ci16*5 + uu+1-(j>>1))*40 + vv + 5 - pxp;
                    bsplit2(pr[0], pr[-1], Bh[ni][kj], Bl[ni][kj]);
                }
            }
#pragma unroll
            for (int mi=0;mi<2;mi++)
#pragma unroll
            for (int ni=0;ni<4;ni++)
                bmma3(c[mi][ni], Ah[mi], Al[mi], Bh[ni], Bl[ni]);
        }
    }
#pragma unroll
    for (int mi=0;mi<2;mi++){
        int co = co0+mrow+mi*16+gp;
        float b0v = bup[co], b1v = bup[co+8];
#pragma unroll
        for (int ni=0;ni<4;ni++){
            int n = ncol+ni*8+2*tig; int uu=n>>5, vv=n&31;
            int oy = 2*(uq*4+uu) + 1 - py;
            int ox = 2*vv + 1 - pxp;
            size_t o0 = (((size_t)(b*C+co))<<12) + oy*64 + ox;
            float v00 = c[mi][ni][0]+b0v, v01 = c[mi][ni][1]+b0v;
            g_coarse[o0] = v00; g_coarse[o0+2] = v01;
            g_y[o0] = v00; g_y[o0+2] = v01;
            size_t o1 = (((size_t)(b*C+co+8))<<12) + oy*64 + ox;
            float v10 = c[mi][ni][2]+b1v, v11 = c[mi][ni][3]+b1v;
            g_coarse[o1] = v10; g_coarse[o1+2] = v11;
            g_y[o1] = v10; g_y[o1+2] = v11;
        }
    }
}

// ---- qkv bf16: grid(32,16), warp m32 x n24, ldmatrix both sides ----
__global__ __launch_bounds__(256) void k_qkv_t(const float* __restrict__ Wm,
                                               const float* __restrict__ bias, int fine) {
    int bh = blockIdx.x, pt = blockIdx.y;
    int b = bh >> 2, h = bh & 3;
    __shared__ unsigned sAh[64*36], sAl[64*36];
    __shared__ unsigned sWh2[96*36], sWl2[96*36];
    int t=threadIdx.x, w=t>>5, lane=t&31, gp=lane>>2, tig=lane&3;
    int mrow=(w>>2)*32, ncol=(w&3)*24;
    int aoff = AOFF(lane,36), boff = BOFF(lane,36), b2off = B2OFF(lane,36);
    if (!fine) {
        const float* src = g_xd + ((size_t)(b*C + h*HD)) * PLANE32 + pt*64;
        for (int idx = t; idx < 2048; idx += 256) {
            int dp = idx >> 6, p = idx & 63;
            float v0 = src[(2*dp)*PLANE32 + p];
            float v1 = src[(2*dp+1)*PLANE32 + p];
            bsplit2(v0, v1, sAh[p*36+dp], sAl[p*36+dp]);
        }
    } else {
        for (int idx = t; idx < 2048; idx += 256) {
            int dp = idx >> 6, p = idx & 63;
            int tok = pt*64 + p;
            int ki = tok >> 2, s = tok & 3;
            int pi = g_topk[bh*KF + ki];
            int yy = ((pi >> 5) << 1) + (s >> 1);
            int xx = ((pi & 31) << 1) + (s & 1);
            size_t base = (((size_t)(b*C + h*HD)) << 12) + (yy << 6) + xx;
            float v0 = g_coarse[base + ((size_t)(2*dp) << 12)];
            float v1 = g_coarse[base + ((size_t)(2*dp+1) << 12)];
            bsplit2(v0, v1, sAh[p*36+dp], sAl[p*36+dp]);
        }
    }
    float* dst = g_qkv + ((size_t)bh * P + pt*64) * 192;
    for (int half = 0; half < 2; half++) {
        __syncthreads();
        for (int idx = t; idx < 3072; idx += 256) {
            int dp = idx / 96, n = idx - 96*dp;
            float v0 = Wm[(2*dp)*192 + half*96 + n];
            float v1 = Wm[(2*dp+1)*192 + half*96 + n];
            bsplit2(v0, v1, sWh2[n*36+dp], sWl2[n*36+dp]);
        }
        __syncthreads();
        float c[2][3][4];
#pragma unroll
        for (int i=0;i<2;i++)
#pragma unroll
        for (int jn=0;jn<3;jn++)
#pragma unroll
        for (int k=0;k<4;k++) c[i][jn][k]=0.f;
#pragma unroll
        for (int kk=0;kk<4;kk++){
            unsigned Ah[2][4], Al[2][4], Bh[3][2], Bl[3][2];
#pragma unroll
            for (int mi=0;mi<2;mi++){
                ldsm4(Ah[mi][0],Ah[mi][1],Ah[mi][2],Ah[mi][3],
                      sAh + (mrow+mi*16)*36 + kk*8 + aoff);
                ldsm4(Al[mi][0],Al[mi][1],Al[mi][2],Al[mi][3],
                      sAl + (mrow+mi*16)*36 + kk*8 + aoff);
            }
            ldsm4(Bh[0][0],Bh[0][1],Bh[1][0],Bh[1][1], sWh2 + ncol*36 + kk*8 + boff);
            ldsm4(Bl[0][0],Bl[0][1],Bl[1][0],Bl[1][1], sWl2 + ncol*36 + kk*8 + boff);
            ldsm2(Bh[2][0],Bh[2][1], sWh2 + (ncol+16)*36 + kk*8 + b2off);
            ldsm2(Bl[2][0],Bl[2][1], sWl2 + (ncol+16)*36 + kk*8 + b2off);
#pragma unroll
            for (int mi=0;mi<2;mi++)
#pragma unroll
            for (int ni=0;ni<3;ni++)
                bmma3(c[mi][ni], Ah[mi], Al[mi], Bh[ni], Bl[ni]);
        }
#pragma unroll
        for (int mi=0;mi<2;mi++){
            int p = mrow+mi*16+gp;
#pragma unroll
            for (int ni=0;ni<3;ni++){
                int n = half*96 + ncol+ni*8+2*tig;
                float bb0 = bias[n], bb1 = bias[n+1];
                *(float2*)(dst + p*192 + n) = make_float2(c[mi][ni][0]+bb0, c[mi][ni][1]+bb1);
                *(float2*)(dst + (p+8)*192 + n) = make_float2(c[mi][ni][2]+bb0, c[mi][ni][3]+bb1);
            }
        }
    }
}

// ---- coarse stats only (no logits write): grid(32,16) ----
__global__ __launch_bounds__(256) void k_logits_s() {
    int bh = blockIdx.x, qt = blockIdx.y;
    __shared__ unsigned sQh[64*36], sQl[64*36];
    __shared__ unsigned sKh[128*36], sKl[128*36];
    __shared__ float sM[64], sS[64], sRm[256], sRs[256];
    int t=threadIdx.x, w=t>>5, lane=t&31, gp=lane>>2, tig=lane&3;
    int mrow=(w>>2)*32, ncol=(w&3)*32, nw=w&3;
    int aoff = AOFF(lane,36), boff = BOFF(lane,36);
    const float* qkv = g_qkv + (size_t)bh*P*192;
    for (int idx=t; idx<1024; idx+=256){
        int r=idx>>4, f4=idx&15;
        float4 v = *(const float4*)(qkv + (qt*64+r)*192 + f4*4);
        bsplit2(v.x, v.y, sQh[r*36+f4*2],   sQl[r*36+f4*2]);
        bsplit2(v.z, v.w, sQh[r*36+f4*2+1], sQl[r*36+f4*2+1]);
    }
    if (t<64){ sM[t]=-1e30f; sS[t]=0.f; }
    for (int s=0; s<8; s++){
        int colbase = s*128;
        __syncthreads();
        for (int idx=t; idx<2048; idx+=256){
            int r=idx>>4, f4=idx&15;
            float4 v = *(const float4*)(qkv + (colbase+r)*192 + 64 + f4*4);
            bsplit2(v.x, v.y, sKh[r*36+f4*2],   sKl[r*36+f4*2]);
            bsplit2(v.z, v.w, sKh[r*36+f4*2+1], sKl[r*36+f4*2+1]);
        }
        __syncthreads();
        float c[2][4][4];
#pragma unroll
        for (int i=0;i<2;i++)
#pragma unroll
        for (int jn=0;jn<4;jn++)
#pragma unroll
        for (int k=0;k<4;k++) c[i][jn][k]=0.f;
#pragma unroll
        for (int kk=0;kk<4;kk++){
            unsigned Ah[2][4], Al[2][4], Bh[4][2], Bl[4][2];
#pragma unroll
            for (int mi=0;mi<2;mi++){
                ldsm4(Ah[mi][0],Ah[mi][1],Ah[mi][2],Ah[mi][3],
                      sQh + (mrow+mi*16)*36 + kk*8 + aoff);
                ldsm4(Al[mi][0],Al[mi][1],Al[mi][2],Al[mi][3],
                      sQl + (mrow+mi*16)*36 + kk*8 + aoff);
            }
            ldsm4(Bh[0][0],Bh[0][1],Bh[1][0],Bh[1][1], sKh + ncol*36 + kk*8 + boff);
            ldsm4(Bl[0][0],Bl[0][1],Bl[1][0],Bl[1][1], sKl + ncol*36 + kk*8 + boff);
            ldsm4(Bh[2][0],Bh[2][1],Bh[3][0],Bh[3][1], sKh + (ncol+16)*36 + kk*8 + boff);
            ldsm4(Bl[2][0],Bl[2][1],Bl[3][0],Bl[3][1], sKl + (ncol+16)*36 + kk*8 + boff);
#pragma unroll
            for (int mi=0;mi<2;mi++)
#pragma unroll
            for (int ni=0;ni<4;ni++)
                bmma3(c[mi][ni], Ah[mi], Al[mi], Bh[ni], Bl[ni]);
        }
#pragma unroll
        for (int i=0;i<2;i++)
#pragma unroll
        for (int jn=0;jn<4;jn++)
#pragma unroll
        for (int k=0;k<4;k++) c[i][jn][k] *= 0.125f;
#pragma unroll
        for (int mi=0;mi<2;mi++)
#pragma unroll
        for (int rh=0;rh<2;rh++){
            float m0 = -1e30f;
#pragma unroll
            for (int ni=0;ni<4;ni++)
                m0 = fmaxf(m0, fmaxf(c[mi][ni][2*rh], c[mi][ni][2*rh+1]));
            m0 = fmaxf(m0, __shfl_xor_sync(0xffffffffu, m0, 1));
            m0 = fmaxf(m0, __shfl_xor_sync(0xffffffffu, m0, 2));
            if (tig==0) sRm[(mrow+mi*16+gp+8*rh)*4 + nw] = m0;
        }
        __syncthreads();
        float mn_[2][2], f_[2][2];
#pragma unroll
        for (int mi=0;mi<2;mi++)
#pragma unroll
        for (int rh=0;rh<2;rh++){
            int r = mrow+mi*16+gp+8*rh;
            float Mc = fmaxf(fmaxf(sRm[r*4],sRm[r*4+1]), fmaxf(sRm[r*4+2],sRm[r*4+3]));
            float mo = sM[r];
            float mnv = fmaxf(mo, Mc);
            mn_[mi][rh] = mnv; f_[mi][rh] = __expf(mo - mnv);
            float s0 = 0.f;
#pragma unroll
            for (int ni=0;ni<4;ni++)
                s0 += __expf(c[mi][ni][2*rh]-mnv) + __expf(c[mi][ni][2*rh+1]-mnv);
            s0 += __shfl_xor_sync(0xffffffffu, s0, 1);
            s0 += __shfl_xor_sync(0xffffffffu, s0, 2);
            if (tig==0) sRs[r*4 + nw] = s0;
        }
        __syncthreads();
        if (nw==0 && tig==0){
#pragma unroll
            for (int mi=0;mi<2;mi++)
#pragma unroll
            for (int rh=0;rh<2;rh++){
                int r = mrow+mi*16+gp+8*rh;
                float Sc = sRs[r*4]+sRs[r*4+1]+sRs[r*4+2]+sRs[r*4+3];
                sS[r] = sS[r]*f_[mi][rh] + Sc;
                sM[r] = mn_[mi][rh];
            }
        }
    }
    __syncthreads();
    if (nw==0 && tig==0){
#pragma unroll
        for (int mi=0;mi<2;mi++)
#pragma unroll
        for (int rh=0;rh<2;rh++){
            int r = mrow+mi*16+gp+8*rh;
            g_sm[bh*1024 + qt*64 + r] = sM[r];
            g_ssi[bh*1024 + qt*64 + r] = 1.f / sS[r];
        }
    }
}

// ---- coarse AV, flash-style recompute (no g_attn), colsum from fragments ----
// grid (32 bh, 16 qt) block 256; warp m32 x n16
__global__ __launch_bounds__(256) void k_av_e() {
    int bh = blockIdx.x, qt = blockIdx.y;
    int b = bh >> 2, h = bh & 3;
    __shared__ unsigned sQh[64*36], sQl[64*36];
    __shared__ unsigned sKPh[64*36], sKPl[64*36];   // K chunk, then reused for P
    __shared__ unsigned sVh[64*20], sVl[64*20];
    __shared__ float sMv[64], sSv[64], scol[64];
    int t=threadIdx.x, w=t>>5, lane=t&31, gp=lane>>2, tig=lane&3;
    int mrow=(w>>2)*32, ncol=(w&3)*16;
    int aoff=AOFF(lane,36), boff=BOFF(lane,36), voff=BOFF(lane,20);
    int nw = w&3;
    const float* qkv = g_qkv + (size_t)bh*P*192;
    for (int idx=t; idx<1024; idx+=256){
        int r=idx>>4, f4=idx&15;
        float4 v = *(const float4*)(qkv + (qt*64+r)*192 + f4*4);
        bsplit2(v.x, v.y, sQh[r*36+f4*2],   sQl[r*36+f4*2]);
        bsplit2(v.z, v.w, sQh[r*36+f4*2+1], sQl[r*36+f4*2+1]);
    }
    if (t<64){ sMv[t]=g_sm[bh*1024+qt*64+t]; sSv[t]=g_ssi[bh*1024+qt*64+t]; }
    __syncthreads();
    float m_[2][2], si_[2][2];
#pragma unroll
    for (int mi=0;mi<2;mi++)
#pragma unroll
    for (int rh=0;rh<2;rh++){
        int r = mrow+mi*16+gp+8*rh;
        m_[mi][rh] = sMv[r]; si_[mi][rh] = sSv[r];
    }
    float o[2][2][4];
#pragma unroll
    for (int i=0;i<2;i++)
#pragma unroll
    for (int j=0;j<2;j++)
#pragma unroll
    for (int k=0;k<4;k++) o[i][j][k]=0.f;
    const float* vptr = qkv + 128;
    for (int kc=0; kc<16; kc++){
        __syncthreads();
        if (t<64) scol[t]=0.f;
        for (int idx=t; idx<1024; idx+=256){
            int r=idx>>4, f4=idx&15;
            float4 v = *(const float4*)(qkv + (kc*64+r)*192 + 64 + f4*4);
            bsplit2(v.x, v.y, sKPh[r*36+f4*2],   sKPl[r*36+f4*2]);
            bsplit2(v.z, v.w, sKPh[r*36+f4*2+1], sKPl[r*36+f4*2+1]);
        }
        __syncthreads();
        // QK^T
        float c[2][2][4];
#pragma unroll
        for (int i=0;i<2;i++)
#pragma unroll
        for (int j=0;j<2;j++)
#pragma unroll
        for (int k=0;k<4;k++) c[i][j][k]=0.f;
#pragma unroll
        for (int kk=0;kk<4;kk++){
            unsigned Ah[2][4], Al[2][4], Bh[2][2], Bl[2][2];
#pragma unroll
            for (int mi=0;mi<2;mi++){
                ldsm4(Ah[mi][0],Ah[mi][1],Ah[mi][2],Ah[mi][3],
                      sQh + (mrow+mi*16)*36 + kk*8 + aoff);
                ldsm4(Al[mi][0],Al[mi][1],Al[mi][2],Al[mi][3],
                      sQl + (mrow+mi*16)*36 + kk*8 + aoff);
            }
            ldsm4(Bh[0][0],Bh[0][1],Bh[1][0],Bh[1][1], sKPh + ncol*36 + kk*8 + boff);
            ldsm4(Bl[0][0],Bl[0][1],Bl[1][0],Bl[1][1], sKPl + ncol*36 + kk*8 + boff);
#pragma unroll
            for (int mi=0;mi<2;mi++)
#pragma unroll
            for (int ni=0;ni<2;ni++)
                bmma3(c[mi][ni], Ah[mi], Al[mi], Bh[ni], Bl[ni]);
        }
        // p = exp(c*0.125 - m) * (1/s)
#pragma unroll
        for (int mi=0;mi<2;mi++)
#pragma unroll
        for (int ni=0;ni<2;ni++)
#pragma unroll
        for (int k=0;k<4;k++)
            c[mi][ni][k] = __expf(c[mi][ni][k]*0.125f - m_[mi][k>>1]) * si_[mi][k>>1];
        // colsum partials: per lane sum over mi, rh; shuffle over gp; gp==0 lanes add
#pragma unroll
        for (int ni=0;ni<2;ni++)
#pragma unroll
        for (int kb=0;kb<2;kb++){
            float part = c[0][ni][kb] + c[0][ni][2+kb] + c[1][ni][kb] + c[1][ni][2+kb];
            part += __shfl_xor_sync(0xffffffffu, part, 4);
            part += __shfl_xor_sync(0xffffffffu, part, 8);
            part += __shfl_xor_sync(0xffffffffu, part, 16);
            if (gp==0) atomicAdd(&scol[ncol + ni*8 + 2*tig + kb], part);
        }
        __syncthreads();
        if (t<64) g_part[((size_t)bh*16+qt)*1024 + kc*64 + t] = scol[t];
        // pack P into sKP (K fragments consumed; all warps past QK^T reads)
#pragma unroll
        for (int mi=0;mi<2;mi++){
            int r0 = mrow+mi*16+gp;
#pragma unroll
            for (int ni=0;ni<2;ni++){
                int p2 = nw*8 + ni*4 + tig;
                bsplit2(c[mi][ni][0], c[mi][ni][1], sKPh[r0*36 + p2],     sKPl[r0*36 + p2]);
                bsplit2(c[mi][ni][2], c[mi][ni][3], sKPh[(r0+8)*36 + p2], sKPl[(r0+8)*36 + p2]);
            }
        }
        // AV in two V halves
#pragma unroll
        for (int vh=0; vh<2; vh++){
            __syncthreads();
            for (int idx=t; idx<1024; idx+=256){
                int d=idx&63, tp=idx>>6;
                float v0 = vptr[(size_t)(kc*64+vh*32+2*tp)*192 + d];
                float v1 = vptr[(size_t)(kc*64+vh*32+2*tp+1)*192 + d];
                bsplit2(v0, v1, sVh[d*20+tp], sVl[d*20+tp]);
            }
            __syncthreads();
#pragma unroll
            for (int kl=0;kl<2;kl++){
                unsigned Ah[2][4], Al[2][4], Bh[2][2], Bl[2][2];
                int kk = vh*2 + kl;
#pragma unroll
                for (int mi=0;mi<2;mi++){
                    ldsm4(Ah[mi][0],Ah[mi][1],Ah[mi][2],Ah[mi][3],
                          sKPh + (mrow+mi*16)*36 + kk*8 + aoff);
                    ldsm4(Al[mi][0],Al[mi][1],Al[mi][2],Al[mi][3],
                          sKPl + (mrow+mi*16)*36 + kk*8 + aoff);
                }
                ldsm4(Bh[0][0],Bh[0][1],Bh[1][0],Bh[1][1], sVh + ncol*20 + kl*8 + voff);
                ldsm4(Bl[0][0],Bl[0][1],Bl[1][0],Bl[1][1], sVl + ncol*20 + kl*8 + voff);
#pragma unroll
                for (int mi=0;mi<2;mi++)
#pragma unroll
                for (int ni=0;ni<2;ni++)
                    bmma3(o[mi][ni], Ah[mi], Al[mi], Bh[ni], Bl[ni]);
            }
        }
    }
#pragma unroll
    for (int mi=0;mi<2;mi++)
#pragma unroll
    for (int ni=0;ni<2;ni++){
        int row = qt*64 + mrow+mi*16+gp;
        int d0 = ncol+ni*8+2*tig;
        g_outc[((size_t)(b*C + h*HD + d0  ))*PLANE32 + row] = o[mi][ni][0];
        g_outc[((size_t)(b*C + h*HD + d0+1))*PLANE32 + row] = o[mi][ni][1];
        g_outc[((size_t)(b*C + h*HD + d0  ))*PLANE32 + row + 8] = o[mi][ni][2];
        g_outc[((size_t)(b*C + h*HD + d0+1))*PLANE32 + row + 8] = o[mi][ni][3];
    }
}

// ---- topk: sum partials then bitonic ----
__global__ __launch_bounds__(512) void k_topk() {
    int bh = blockIdx.x;
    __shared__ float sv[1024];
    __shared__ int si[1024];
    int t = threadIdx.x;
    float a0=0.f, a1=0.f;
#pragma unroll
    for (int j=0;j<16;j++){
        a0 += g_part[((size_t)bh*16+j)*1024 + t];
        a1 += g_part[((size_t)bh*16+j)*1024 + t + 512];
    }
    sv[t]=a0; si[t]=t; sv[t+512]=a1; si[t+512]=t+512;
    __syncthreads();
    for (int k = 2; k <= 1024; k <<= 1) {
        for (int j = k >> 1; j > 0; j >>= 1) {
#pragma unroll
            for (int mm = 0; mm < 2; mm++) {
                int i = t + mm*512;
                int l = i ^ j;
                if (l > i) {
                    float vi = sv[i], vl = sv[l];
                    int ii = si[i], il = si[l];
                    bool before = (vi > vl) || (vi == vl && ii < il);
                    bool keep = ((i & k) == 0) ? before : !before;
                    if (!keep) { sv[i] = vl; sv[l] = vi; si[i] = il; si[l] = ii; }
                }
            }
            __syncthreads();
        }
    }
    if (t < 256) g_topk[bh*KF + t] = si[t];
}

// ---- flash attention (fine path), scatter fused into epilogue ----
__global__ __launch_bounds__(256) void k_flash() {
    int bh = blockIdx.x, qt = blockIdx.y;
    __shared__ unsigned sQh[64*36], sQl[64*36];
    __shared__ unsigned sKPh[64*36], sKPl[64*36];
    __shared__ unsigned sVh[64*20], sVl[64*20];
    __shared__ float sM[64], sS[64];
    float* sRm = (float*)sVh;
    float* sRs = (float*)sVl;
    int t=threadIdx.x, w=t>>5, lane=t&31, gp=lane>>2, tig=lane&3;
    int mrow=(w>>2)*32, ncol=(w&3)*16;
    int aoff=AOFF(lane,36), boff=BOFF(lane,36), voff=BOFF(lane,20);
    int nw = w&3;
    const float* qkv = g_qkv + (size_t)bh*P*192;
    for (int idx=t; idx<1024; idx+=256){
        int r=idx>>4, f4=idx&15;
        float4 v = *(const float4*)(qkv + (qt*64+r)*192 + f4*4);
        bsplit2(v.x, v.y, sQh[r*36+f4*2],   sQl[r*36+f4*2]);
        bsplit2(v.z, v.w, sQh[r*36+f4*2+1], sQl[r*36+f4*2+1]);
    }
    if (t < 64){ sM[t] = -1e30f; sS[t] = 0.f; }
    float o[2][2][4];
#pragma unroll
    for (int i=0;i<2;i++)
#pragma unroll
    for (int j=0;j<2;j++)
#pragma unroll
    for (int k=0;k<4;k++) o[i][j][k]=0.f;
    const float* vptr = qkv + 128;
    for (int kc=0; kc<16; kc++){
        __syncthreads();
        for (int idx=t; idx<1024; idx+=256){
            int r=idx>>4, f4=idx&15;
            float4 v = *(const float4*)(qkv + (kc*64+r)*192 + 64 + f4*4);
            bsplit2(v.x, v.y, sKPh[r*36+f4*2],   sKPl[r*36+f4*2]);
            bsplit2(v.z, v.w, sKPh[r*36+f4*2+1], sKPl[r*36+f4*2+1]);
        }
        __syncthreads();
        float c[2][2][4];
#pragma unroll
        for (int i=0;i<2;i++)
#pragma unroll
        for (int j=0;j<2;j++)
#pragma unroll
        for (int k=0;k<4;k++) c[i][j][k]=0.f;
#pragma unroll
        for (int kk=0;kk<4;kk++){
            unsigned Ah[2][4], Al[2][4], Bh[2][2], Bl[2][2];
#pragma unroll
            for (int mi=0;mi<2;mi++){
                ldsm4(Ah[mi][0],Ah[mi][1],Ah[mi][2],Ah[mi][3],
                      sQh + (mrow+mi*16)*36 + kk*8 + aoff);
                ldsm4(Al[mi][0],Al[mi][1],Al[mi][2],Al[mi][3],
                      sQl + (mrow+mi*16)*36 + kk*8 + aoff);
            }
            ldsm4(Bh[0][0],Bh[0][1],Bh[1][0],Bh[1][1], sKPh + ncol*36 + kk*8 + boff);
            ldsm4(Bl[0][0],Bl[0][1],Bl[1][0],Bl[1][1], sKPl + ncol*36 + kk*8 + boff);
#pragma unroll
            for (int mi=0;mi<2;mi++)
#pragma unroll
            for (int ni=0;ni<2;ni++)
                bmma3(c[mi][ni], Ah[mi], Al[mi], Bh[ni], Bl[ni]);
        }
#pragma unroll
        for (int i=0;i<2;i++)
#pragma unroll
        for (int j=0;j<2;j++)
#pragma unroll
        for (int k=0;k<4;k++) c[i][j][k] *= 0.125f;
#pragma unroll
        for (int mi=0;mi<2;mi++)
#pragma unroll
        for (int rh=0;rh<2;rh++){
            float m0 = fmaxf(fmaxf(c[mi][0][2*rh], c[mi][0][2*rh+1]),
                             fmaxf(c[mi][1][2*rh], c[mi][1][2*rh+1]));
            m0 = fmaxf(m0, __shfl_xor_sync(0xffffffffu, m0, 1));
            m0 = fmaxf(m0, __shfl_xor_sync(0xffffffffu, m0, 2));
            if (tig==0) sRm[(mrow+mi*16+gp+8*rh)*4 + nw] = m0;
        }
        __syncthreads();
        float f_[2][2], mn_[2][2];
#pragma unroll
        for (int mi=0;mi<2;mi++)
#pragma unroll
        for (int rh=0;rh<2;rh++){
            int r = mrow+mi*16+gp+8*rh;
            float Mc = fmaxf(fmaxf(sRm[r*4+0], sRm[r*4+1]), fmaxf(sRm[r*4+2], sRm[r*4+3]));
            float mo = sM[r];
            float mnv = fmaxf(mo, Mc);
            mn_[mi][rh] = mnv;
            f_[mi][rh] = __expf(mo - mnv);
        }
#pragma unroll
        for (int mi=0;mi<2;mi++)
#pragma unroll
        for (int ni=0;ni<2;ni++)
#pragma unroll
        for (int k=0;k<4;k++)
            c[mi][ni][k] = __expf(c[mi][ni][k] - mn_[mi][k>>1]);
#pragma unroll
        for (int mi=0;mi<2;mi++)
#pragma unroll
        for (int rh=0;rh<2;rh++){
            float s0 = c[mi][0][2*rh] + c[mi][0][2*rh+1] + c[mi][1][2*rh] + c[mi][1][2*rh+1];
            s0 += __shfl_xor_sync(0xffffffffu, s0, 1);
            s0 += __shfl_xor_sync(0xffffffffu, s0, 2);
            if (tig==0) sRs[(mrow+mi*16+gp+8*rh)*4 + nw] = s0;
        }
        __syncthreads();
#pragma unroll
        for (int mi=0;mi<2;mi++)
#pragma unroll
        for (int ni=0;ni<2;ni++)
#pragma unroll
        for (int k=0;k<4;k++) o[mi][ni][k] *= f_[mi][k>>1];
        if (nw==0 && tig==0){
#pragma unroll
            for (int mi=0;mi<2;mi++)
#pragma unroll
            for (int rh=0;rh<2;rh++){
                int r = mrow+mi*16+gp+8*rh;
                float Sc = sRs[r*4+0]+sRs[r*4+1]+sRs[r*4+2]+sRs[r*4+3];
                sS[r] = sS[r]*f_[mi][rh] + Sc;
                sM[r] = mn_[mi][rh];
            }
        }
#pragma unroll
        for (int mi=0;mi<2;mi++){
            int r0 = mrow+mi*16+gp;
#pragma unroll
            for (int ni=0;ni<2;ni++){
                int p2 = nw*8 + ni*4 + tig;
                bsplit2(c[mi][ni][0], c[mi][ni][1], sKPh[r0*36 + p2],     sKPl[r0*36 + p2]);
                bsplit2(c[mi][ni][2], c[mi][ni][3], sKPh[(r0+8)*36 + p2], sKPl[(r0+8)*36 + p2]);
            }
        }
#pragma unroll
        for (int vh=0; vh<2; vh++){
            __syncthreads();
            for (int idx=t; idx<1024; idx+=256){
                int d=idx&63, tp=idx>>6;
                float v0 = vptr[(size_t)(kc*64+vh*32+2*tp)*192 + d];
                float v1 = vptr[(size_t)(kc*64+vh*32+2*tp+1)*192 + d];
                bsplit2(v0, v1, sVh[d*20+tp], sVl[d*20+tp]);
            }
            __syncthreads();
#pragma unroll
            for (int kl=0;kl<2;kl++){
                unsigned Ah[2][4], Al[2][4], Bh[2][2], Bl[2][2];
                int kk = vh*2 + kl;
#pragma unroll
                for (int mi=0;mi<2;mi++){
                    ldsm4(Ah[mi][0],Ah[mi][1],Ah[mi][2],Ah[mi][3],
                          sKPh + (mrow+mi*16)*36 + kk*8 + aoff);
                    ldsm4(Al[mi][0],Al[mi][1],Al[mi][2],Al[mi][3],
                          sKPl + (mrow+mi*16)*36 + kk*8 + aoff);
                }
                ldsm4(Bh[0][0],Bh[0][1],Bh[1][0],Bh[1][1], sVh + ncol*20 + kl*8 + voff);
                ldsm4(Bl[0][0],Bl[0][1],Bl[1][0],Bl[1][1], sVl + ncol*20 + kl*8 + voff);
#pragma unroll
                for (int mi=0;mi<2;mi++)
#pragma unroll
                for (int ni=0;ni<2;ni++)
                    bmma3(o[mi][ni], Ah[mi], Al[mi], Bh[ni], Bl[ni]);
            }
        }
    }
    __syncthreads();
    {
        int b = bh>>2, h = bh&3;
#pragma unroll
        for (int mi=0;mi<2;mi++){
            float inv0 = 1.f / sS[mrow+mi*16+gp];
            float inv1 = 1.f / sS[mrow+mi*16+gp+8];
            int tok0 = qt*64 + mrow+mi*16+gp;
            int tok1 = tok0 + 8;
            int p0 = g_topk[bh*KF + (tok0>>2)], s0i = tok0&3;
            int p1 = g_topk[bh*KF + (tok1>>2)], s1i = tok1&3;
            int yy0 = ((p0>>5)<<1)+(s0i>>1), xx0 = ((p0&31)<<1)+(s0i&1);
            int yy1 = ((p1>>5)<<1)+(s1i>>1), xx1 = ((p1&31)<<1)+(s1i&1);
            size_t base0 = (((size_t)(b*C + h*HD))<<12) + (yy0<<6) + xx0;
            size_t base1 = (((size_t)(b*C + h*HD))<<12) + (yy1<<6) + xx1;
#pragma unroll
            for (int ni=0;ni<2;ni++){
                int d0 = ncol+ni*8+2*tig;
                g_y[base0 + ((size_t)d0<<12)]     += o[mi][ni][0]*inv0;
                g_y[base0 + ((size_t)(d0+1)<<12)] += o[mi][ni][1]*inv0;
                g_y[base1 + ((size_t)d0<<12)]     += o[mi][ni][2]*inv1;
                g_y[base1 + ((size_t)(d0+1)<<12)] += o[mi][ni][3]*inv1;
            }
        }
    }
}

// ---- depthwise 3x3 + BN + relu6 (smem tiled): grid(2048) ----
__global__ __launch_bounds__(256) void k_dw(const float* __restrict__ wdw,
                                            const float* __restrict__ g,
                                            const float* __restrict__ bb,
                                            const float* __restrict__ m,
                                            const float* __restrict__ vv) {
    int bc = blockIdx.x;
    __shared__ float sp[66*66];
    int t = threadIdx.x;
    const float* plane = g_y + ((size_t)bc<<12);
    for (int idx=t; idx<4356; idx+=256){
        int r = idx/66, cx = idx - r*66;
        int iy = r-1, ix = cx-1;
        sp[idx] = (iy>=0 && iy<64 && ix>=0 && ix<64) ? plane[(iy<<6)+ix] : 0.f;
    }
    __syncthreads();
    int c = bc & 255;
    const float* wc = wdw + c*9;
    float w0=wc[0],w1=wc[1],w2=wc[2],w3=wc[3],w4=wc[4],w5=wc[5],w6=wc[6],w7=wc[7],w8=wc[8];
    float sc = g[c] * rsqrtf(vv[c] + 1e-5f);
    float off = bb[c] - m[c] * sc;
#pragma unroll
    for (int i=0;i<16;i++){
        int p = t + i*256;
        int y = p>>6, x = p&63;
        const float* s0 = sp + y*66 + x;
        float s = w0*s0[0] + w1*s0[1] + w2*s0[2]
                + w3*s0[66] + w4*s0[67] + w5*s0[68]
                + w6*s0[132] + w7*s0[133] + w8*s0[134];
        float r = s*sc + off;
        g_yd[((size_t)bc<<12) + p] = fminf(fmaxf(r, 0.f), 6.f);
    }
}

// ---- pointwise bf16: grid(8,32,4), ldmatrix both sides ----
__global__ __launch_bounds__(256) void k_pw_t(const float* __restrict__ g,
                                              const float* __restrict__ bb,
                                              const float* __restrict__ m,
                                              const float* __restrict__ vv,
                                              float* __restrict__ out) {
    int b = blockIdx.x, sp = blockIdx.y, cg = blockIdx.z;
    __shared__ unsigned sWh[64*20], sWl[64*20];
    __shared__ unsigned sXh[128*20], sXl[128*20];
    int t=threadIdx.x, w=t>>5, lane=t&31, gp=lane>>2, tig=lane&3;
    int mrow=(w>>2)*32, ncol=(w&3)*32;
    int aoff = AOFF(lane,20), boff = BOFF(lane,20);
    float c[2][4][4];
#pragma unroll
    for (int i=0;i<2;i++)
#pragma unroll
    for (int jn=0;jn<4;jn++)
#pragma unroll
    for (int k=0;k<4;k++) c[i][jn][k]=0.f;
    const float* xin = g_yd + (size_t)b * C * HW + sp * 128;
    for (int cc = 0; cc < 8; cc++) {
        __syncthreads();
        {
            int idx = t;
            int co=idx>>2, c4=(idx&3)<<2;
            *(uint4*)(sWh + co*20 + c4) = *(const uint4*)(g_pwh + (size_t)(cg*64+co)*128 + cc*16 + c4);
            *(uint4*)(sWl + co*20 + c4) = *(const uint4*)(g_pwl + (size_t)(cg*64+co)*128 + cc*16 + c4);
        }
        for (int idx=t; idx<2048; idx+=256){
            int px = idx&127, kp = idx>>7;
            float v0 = xin[(size_t)(cc*32+2*kp)*HW + px];
            float v1 = xin[(size_t)(cc*32+2*kp+1)*HW + px];
            bsplit2(v0, v1, sXh[px*20+kp], sXl[px*20+kp]);
        }
        __syncthreads();
#pragma unroll
        for (int kk=0;kk<2;kk++){
            unsigned Ah[2][4], Al[2][4], Bh[4][2], Bl[4][2];
#pragma unroll
            for (int mi=0;mi<2;mi++){
                ldsm4(Ah[mi][0],Ah[mi][1],Ah[mi][2],Ah[mi][3],
                      sWh + (mrow+mi*16)*20 + kk*8 + aoff);
                ldsm4(Al[mi][0],Al[mi][1],Al[mi][2],Al[mi][3],
                      sWl + (mrow+mi*16)*20 + kk*8 + aoff);
            }
            ldsm4(Bh[0][0],Bh[0][1],Bh[1][0],Bh[1][1], sXh + ncol*20 + kk*8 + boff);
            ldsm4(Bl[0][0],Bl[0][1],Bl[1][0],Bl[1][1], sXl + ncol*20 + kk*8 + boff);
            ldsm4(Bh[2][0],Bh[2][1],Bh[3][0],Bh[3][1], sXh + (ncol+16)*20 + kk*8 + boff);
            ldsm4(Bl[2][0],Bl[2][1],Bl[3][0],Bl[3][1], sXl + (ncol+16)*20 + kk*8 + boff);
#pragma unroll
            for (int mi=0;mi<2;mi++)
#pragma unroll
            for (int ni=0;ni<4;ni++)
                bmma3(c[mi][ni], Ah[mi], Al[mi], Bh[ni], Bl[ni]);
        }
    }
#pragma unroll
    for (int mi=0;mi<2;mi++){
        int co = cg*64 + mrow+mi*16+gp;
        float sc0 = g[co] * rsqrtf(vv[co] + 1e-5f);
        float of0 = bb[co] - m[co] * sc0;
        float sc1 = g[co+8] * rsqrtf(vv[co+8] + 1e-5f);
        float of1 = bb[co+8] - m[co+8] * sc1;
#pragma unroll
        for (int ni=0;ni<4;ni++){
            int px = sp*128 + ncol+ni*8+2*tig;
            float r0 = fminf(fmaxf(c[mi][ni][0]*sc0 + of0, 0.f), 6.f);
            float r1 = fminf(fmaxf(c[mi][ni][1]*sc0 + of0, 0.f), 6.f);
            float r2 = fminf(fmaxf(c[mi][ni][2]*sc1 + of1, 0.f), 6.f);
            float r3 = fminf(fmaxf(c[mi][ni][3]*sc1 + of1, 0.f), 6.f);
            *(float2*)(out + ((size_t)(b*C+co))*HW + px)   = make_float2(r0, r1);
            *(float2*)(out + ((size_t)(b*C+co+8))*HW + px) = make_float2(r2, r3);
        }
    }
}

extern "C" void kernel_launch(void* const* d_in, const int* in_sizes, int n_in,
                              void* d_out, int out_size) {
    const float* x       = (const float*)d_in[0];
    const float* w_down  = (const float*)d_in[1];
    const float* b_down  = (const float*)d_in[2];
    const float* w_qkv_c = (const float*)d_in[3];
    const float* b_qkv_c = (const float*)d_in[4];
    const float* w_up    = (const float*)d_in[5];
    const float* b_up    = (const float*)d_in[6];
    const float* w_qkv_f = (const float*)d_in[7];
    const float* b_qkv_f = (const float*)d_in[8];
    const float* w_dw    = (const float*)d_in[9];
    const float* bn_dw_g = (const float*)d_in[10];
    const float* bn_dw_b = (const float*)d_in[11];
    const float* bn_dw_m = (const float*)d_in[12];
    const float* bn_dw_v = (const float*)d_in[13];
    const float* w_pw    = (const float*)d_in[14];
    const float* bn_pw_g = (const float*)d_in[15];
    const float* bn_pw_b = (const float*)d_in[16];
    const float* bn_pw_m = (const float*)d_in[17];
    const float* bn_pw_v = (const float*)d_in[18];
    float* out = (float*)d_out;

    k_prep_wd<<<2048, 256>>>(w_down);
    k_wt<<<2048, 256>>>(w_up);
    k_prep_pw<<<128, 256>>>(w_pw);

    // ---- coarse path (no materialized attention) ----
    k_down_t<<<dim3(128, 4), 256>>>(x, b_down);
    k_qkv_t<<<dim3(32, 16), 256>>>(w_qkv_c, b_qkv_c, 0);
    k_logits_s<<<dim3(32, 16), 256>>>();
    k_av_e<<<dim3(32, 16), 256>>>();
    k_topk<<<32, 512>>>();
    k_up_t<<<dim3(64, 16), 256>>>(b_up);

    // ---- fine path (flash-fused, scatter in epilogue) ----
    k_qkv_t<<<dim3(32, 16), 256>>>(w_qkv_f, b_qkv_f, 1);
    k_flash<<<dim3(32, 16), 256>>>();

    // ---- feed-forward ----
    k_dw<<<2048, 256>>>(w_dw, bn_dw_g, bn_dw_b, bn_dw_m, bn_dw_v);
    k_pw_t<<<dim3(8, 32, 4), 256>>>(bn_pw_g, bn_pw_b, bn_pw_m, bn_pw_v, out);
}

// round 16
// speedup vs baseline: 1.0899x; 1.0899x over previous
#include <cuda_runtime.h>
#include <math.h>

#define BATCH 8
#define C 256
#define NH 4
#define HD 64
#define P 1024
#define KF 256
#define HW 4096
#define PLANE32 1024

__device__ float g_xd[BATCH*C*PLANE32];
__device__ float g_qkv[BATCH*NH*P*192];
__device__ float g_attn[(size_t)BATCH*NH*P*P];
__device__ float g_outc[BATCH*C*PLANE32];
__device__ float g_sm[32*1024], g_ssi[32*1024];
__device__ float g_part[32*16*1024];
__device__ int   g_topk[32*KF];
__device__ float g_y[BATCH*C*HW];
__device__ unsigned g_ydh[BATCH*128*HW], g_ydl[BATCH*128*HW];
__device__ unsigned g_wdh[256*2048], g_wdl[256*2048];
__device__ unsigned g_wuh[4*256*512], g_wul[4*256*512];
__device__ unsigned g_pwh[256*128],  g_pwl[256*128];

// ---- bf16 helpers ----
__device__ __forceinline__ unsigned bpack(float x0, float x1){
    unsigned r; asm("cvt.rn.bf16x2.f32 %0, %1, %2;" : "=r"(r) : "f"(x1), "f"(x0)); return r;
}
__device__ __forceinline__ void bsplit2(float x0, float x1, unsigned &h, unsigned &l){
    h = bpack(x0, x1);
    l = bpack(x0 - __uint_as_float(h << 16), x1 - __uint_as_float(h & 0xFFFF0000u));
}
__device__ __forceinline__ void bmma(float* c, unsigned a0,unsigned a1,unsigned a2,unsigned a3,
                                     unsigned b0,unsigned b1){
    asm volatile("mma.sync.aligned.m16n8k16.row.col.f32.bf16.bf16.f32 "
        "{%0,%1,%2,%3}, {%4,%5,%6,%7}, {%8,%9}, {%0,%1,%2,%3};"
        : "+f"(c[0]),"+f"(c[1]),"+f"(c[2]),"+f"(c[3])
        : "r"(a0),"r"(a1),"r"(a2),"r"(a3),"r"(b0),"r"(b1));
}
__device__ __forceinline__ void bmma3(float* c, const unsigned* Ah, const unsigned* Al,
                                      const unsigned* Bh, const unsigned* Bl){
    bmma(c, Ah[0],Ah[1],Ah[2],Ah[3], Bh[0],Bh[1]);
    bmma(c, Ah[0],Ah[1],Ah[2],Ah[3], Bl[0],Bl[1]);
    bmma(c, Al[0],Al[1],Al[2],Al[3], Bh[0],Bh[1]);
}
__device__ __forceinline__ void ldsm4(unsigned &r0, unsigned &r1, unsigned &r2, unsigned &r3,
                                      const unsigned* p){
    unsigned a = (unsigned)__cvta_generic_to_shared(p);
    asm volatile("ldmatrix.sync.aligned.m8n8.x4.shared.b16 {%0,%1,%2,%3}, [%4];"
        : "=r"(r0),"=r"(r1),"=r"(r2),"=r"(r3) : "r"(a));
}
__device__ __forceinline__ void ldsm2(unsigned &r0, unsigned &r1, const unsigned* p){
    unsigned a = (unsigned)__cvta_generic_to_shared(p);
    asm volatile("ldmatrix.sync.aligned.m8n8.x2.shared.b16 {%0,%1}, [%2];"
        : "=r"(r0),"=r"(r1) : "r"(a));
}
#define AOFF(lane,s) (((lane)&15)*(s) + (((lane)>>4)<<2))
#define BOFF(lane,s) (((((lane)>>4)<<3)+((lane)&7))*(s) + ((((lane)>>3)&1)<<2))
#define B2OFF(lane,s) ((((lane)&7))*(s) + ((((lane)>>3)&1)<<2))

// ---- weight prep ----
__global__ __launch_bounds__(256) void k_prep_wd(const float* __restrict__ w){
    int i = blockIdx.x*256 + threadIdx.x;
    float2 v = *(const float2*)(w + 2*(size_t)i);
    bsplit2(v.x, v.y, g_wdh[i], g_wdl[i]);
}
__global__ __launch_bounds__(256) void k_wt(const float* __restrict__ wup){
    int idx = blockIdx.x*256 + threadIdx.x;
    int cls = idx>>17, co = (idx>>9)&255, kp = idx&511;
    int py = cls>>1, pxp = cls&1;
    int ci = kp>>1, j0 = (kp&1)*2;
    int ky0 = py + ((j0>>1)<<1);
    float v0 = wup[((size_t)ci*256+co)*16 + ky0*4 + pxp];
    float v1 = wup[((size_t)ci*256+co)*16 + ky0*4 + pxp + 2];
    bsplit2(v0, v1, g_wuh[idx], g_wul[idx]);
}
__global__ __launch_bounds__(256) void k_prep_pw(const float* __restrict__ w){
    int i = blockIdx.x*256 + threadIdx.x;
    float2 v = *(const float2*)(w + 2*(size_t)i);
    bsplit2(v.x, v.y, g_pwh[i], g_pwl[i]);
}

// ---- down conv bf16 (frozen r12): grid(128,4), warp m32 x n16 ----
__global__ __launch_bounds__(256) void k_down_t(const float* __restrict__ x,
                                                const float* __restrict__ bias){
    int b = blockIdx.x>>4, oyp = blockIdx.x&15;
    int co0 = blockIdx.y*64;
    __shared__ unsigned sWh[64*36], sWl[64*36];
    __shared__ float sraw[4*6*72];
    int t=threadIdx.x, w=t>>5, lane=t&31, gp=lane>>2, tig=lane&3;
    int mrow=(w>>2)*32, ncol=(w&3)*16;
    int aoff = AOFF(lane,36);
    float c[2][2][4];
#pragma unroll
    for (int i=0;i<2;i++)
#pragma unroll
    for (int jn=0;jn<2;jn++)
#pragma unroll
    for (int k=0;k<4;k++) c[i][jn][k]=0.f;
    for (int cc=0; cc<64; cc++){
        __syncthreads();
        for (int idx=t; idx<512; idx+=256){
            int co=idx>>3, c4=(idx&7)<<2;
            *(uint4*)(sWh + co*36 + c4) = *(const uint4*)(g_wdh + (size_t)(co0+co)*2048 + cc*32 + c4);
            *(uint4*)(sWl + co*36 + c4) = *(const uint4*)(g_wdl + (size_t)(co0+co)*2048 + cc*32 + c4);
        }
        int ci0 = cc*4;
        for (int idx=t; idx<384; idx+=256){
            int rowid = idx>>4, c4=(idx&15)<<2;
            int ci4 = rowid/6, r = rowid - ci4*6;
            int iy = oyp*4 - 1 + r;
            float4 v = make_float4(0.f,0.f,0.f,0.f);
            if (iy>=0 && iy<64)
                v = *(const float4*)(x + (((size_t)(b*C + ci0+ci4))<<12) + (iy<<6) + c4);
            *(float4*)(sraw + rowid*72 + 4 + c4) = v;
        }
        if (t<24){ sraw[t*72+3]=0.f; sraw[t*72+68]=0.f; }
        __syncthreads();
#pragma unroll
        for (int kk=0;kk<4;kk++){
            unsigned Ah[2][4], Al[2][4], Bh[2][2], Bl[2][2];
#pragma unroll
            for (int mi=0;mi<2;mi++){
                ldsm4(Ah[mi][0],Ah[mi][1],Ah[mi][2],Ah[mi][3],
                      sWh + (mrow+mi*16)*36 + kk*8 + aoff);
                ldsm4(Al[mi][0],Al[mi][1],Al[mi][2],Al[mi][3],
                      sWl + (mrow+mi*16)*36 + kk*8 + aoff);
            }
#pragma unroll
            for (int ni=0;ni<2;ni++){
                int n = ncol+ni*8+gp; int opy=n>>5, opx=n&31;
#pragma unroll
                for (int kj=0;kj<2;kj++){
                    int k0 = kk*16 + kj*8 + 2*tig;
                    int ci4=k0>>4, tap=k0&15, ky=tap>>2, kx=tap&3;
                    const float* pr = sraw + (ci4*6 + 2*opy+ky)*72 + 3 + 2*opx + kx;
                    bsplit2(pr[0], pr[1], Bh[ni][kj], Bl[ni][kj]);
                }
            }
#pragma unroll
            for (int mi=0;mi<2;mi++)
#pragma unroll
            for (int ni=0;ni<2;ni++)
                bmma3(c[mi][ni], Ah[mi], Al[mi], Bh[ni], Bl[ni]);
        }
    }
#pragma unroll
    for (int mi=0;mi<2;mi++){
        int co = co0+mrow+mi*16+gp;
        float b0v = bias[co], b1v = bias[co+8];
#pragma unroll
        for (int ni=0;ni<2;ni++){
            int n = ncol+ni*8+2*tig;
            size_t o = ((size_t)(b*C+co)<<10) + oyp*64 + n;
            *(float2*)(g_xd + o) = make_float2(c[mi][ni][0]+b0v, c[mi][ni][1]+b0v);
            *(float2*)(g_xd + o + (8<<10)) = make_float2(c[mi][ni][2]+b1v, c[mi][ni][3]+b1v);
        }
    }
}

// ---- convT bf16: grid(64,16); writes g_y only ----
__global__ __launch_bounds__(256) void k_up_t(const float* __restrict__ bup){
    int b = blockIdx.x>>3, uq = blockIdx.x&7;
    int cls = blockIdx.y>>2, co0 = (blockIdx.y&3)*64;
    int py = cls>>1, pxp = cls&1;
    __shared__ unsigned sWh[64*36], sWl[64*36];
    __shared__ float sraw[16*5*40];
    int t=threadIdx.x, w=t>>5, lane=t&31, gp=lane>>2, tig=lane&3;
    int mrow=(w>>2)*32, ncol=(w&3)*32;
    int aoff = AOFF(lane,36);
    float c[2][4][4];
#pragma unroll
    for (int i=0;i<2;i++)
#pragma unroll
    for (int jn=0;jn<4;jn++)
#pragma unroll
    for (int k=0;k<4;k++) c[i][jn][k]=0.f;
    for (int cc=0; cc<16; cc++){
        __syncthreads();
        for (int idx=t; idx<512; idx+=256){
            int co=idx>>3, c4=(idx&7)<<2;
            size_t s = (size_t)cls*131072 + (size_t)(co0+co)*512 + cc*32 + c4;
            *(uint4*)(sWh + co*36 + c4) = *(const uint4*)(g_wuh + s);
            *(uint4*)(sWl + co*36 + c4) = *(const uint4*)(g_wul + s);
        }
        int ci0 = cc*16;
        for (int idx=t; idx<640; idx+=256){
            int rowid=idx>>3, c4=(idx&7)<<2;
            int ci16=rowid/5, rr=rowid-ci16*5;
            int iy = uq*4 - py + rr;
            float4 v = make_float4(0.f,0.f,0.f,0.f);
            if (iy>=0 && iy<32)
                v = *(const float4*)(g_outc + (((size_t)(b*C+ci0+ci16))<<10) + (iy<<5) + c4);
            *(float4*)(sraw + rowid*40 + 4 + c4) = v;
        }
        if (t<80){ sraw[t*40+3]=0.f; sraw[t*40+36]=0.f; }
        __syncthreads();
#pragma unroll
        for (int kk=0;kk<4;kk++){
            unsigned Ah[2][4], Al[2][4], Bh[4][2], Bl[4][2];
#pragma unroll
            for (int mi=0;mi<2;mi++){
                ldsm4(Ah[mi][0],Ah[mi][1],Ah[mi][2],Ah[mi][3],
                      sWh + (mrow+mi*16)*36 + kk*8 + aoff);
                ldsm4(Al[mi][0],Al[mi][1],Al[mi][2],Al[mi][3],
                      sWl + (mrow+mi*16)*36 + kk*8 + aoff);
            }
#pragma unroll
            for (int ni=0;ni<4;ni++){
                int n = ncol+ni*8+gp; int uu=n>>5, vv=n&31;
#pragma unroll
                for (int kj=0;kj<2;kj++){
                    int k0 = kk*16 + kj*8 + 2*tig;
                    int ci16=k0>>2, j=k0&3;
                    const float* pr = sraw + (ci16*5 + uu+1-(j>>1))*40 + vv + 5 - pxp;
                    bsplit2(pr[0], pr[-1], Bh[ni][kj], Bl[ni][kj]);
                }
            }
#pragma unroll
            for (int mi=0;mi<2;mi++)
#pragma unroll
            for (int ni=0;ni<4;ni++)
                bmma3(c[mi][ni], Ah[mi], Al[mi], Bh[ni], Bl[ni]);
        }
    }
#pragma unroll
    for (int mi=0;mi<2;mi++){
        int co = co0+mrow+mi*16+gp;
        float b0v = bup[co], b1v = bup[co+8];
#pragma unroll
        for (int ni=0;ni<4;ni++){
            int n = ncol+ni*8+2*tig; int uu=n>>5, vv=n&31;
            int oy = 2*(uq*4+uu) + 1 - py;
            int ox = 2*vv + 1 - pxp;
            size_t o0 = (((size_t)(b*C+co))<<12) + oy*64 + ox;
            g_y[o0]   = c[mi][ni][0]+b0v;
            g_y[o0+2] = c[mi][ni][1]+b0v;
            size_t o1 = (((size_t)(b*C+co+8))<<12) + oy*64 + ox;
            g_y[o1]   = c[mi][ni][2]+b1v;
            g_y[o1+2] = c[mi][ni][3]+b1v;
        }
    }
}

// ---- qkv bf16: grid(32,16), warp m32 x n24; fine gathers from g_y ----
__global__ __launch_bounds__(256) void k_qkv_t(const float* __restrict__ Wm,
                                               const float* __restrict__ bias, int fine) {
    int bh = blockIdx.x, pt = blockIdx.y;
    int b = bh >> 2, h = bh & 3;
    __shared__ unsigned sAh[64*36], sAl[64*36];
    __shared__ unsigned sWh2[96*36], sWl2[96*36];
    int t=threadIdx.x, w=t>>5, lane=t&31, gp=lane>>2, tig=lane&3;
    int mrow=(w>>2)*32, ncol=(w&3)*24;
    int aoff = AOFF(lane,36), boff = BOFF(lane,36), b2off = B2OFF(lane,36);
    if (!fine) {
        const float* src = g_xd + ((size_t)(b*C + h*HD)) * PLANE32 + pt*64;
        for (int idx = t; idx < 2048; idx += 256) {
            int dp = idx >> 6, p = idx & 63;
            float v0 = src[(2*dp)*PLANE32 + p];
            float v1 = src[(2*dp+1)*PLANE32 + p];
            bsplit2(v0, v1, sAh[p*36+dp], sAl[p*36+dp]);
        }
    } else {
        for (int idx = t; idx < 2048; idx += 256) {
            int dp = idx >> 6, p = idx & 63;
            int tok = pt*64 + p;
            int ki = tok >> 2, s = tok & 3;
            int pi = g_topk[bh*KF + ki];
            int yy = ((pi >> 5) << 1) + (s >> 1);
            int xx = ((pi & 31) << 1) + (s & 1);
            size_t base = (((size_t)(b*C + h*HD)) << 12) + (yy << 6) + xx;
            float v0 = g_y[base + ((size_t)(2*dp) << 12)];
            float v1 = g_y[base + ((size_t)(2*dp+1) << 12)];
            bsplit2(v0, v1, sAh[p*36+dp], sAl[p*36+dp]);
        }
    }
    float* dst = g_qkv + ((size_t)bh * P + pt*64) * 192;
    for (int half = 0; half < 2; half++) {
        __syncthreads();
        for (int idx = t; idx < 3072; idx += 256) {
            int dp = idx / 96, n = idx - 96*dp;
            float v0 = Wm[(2*dp)*192 + half*96 + n];
            float v1 = Wm[(2*dp+1)*192 + half*96 + n];
            bsplit2(v0, v1, sWh2[n*36+dp], sWl2[n*36+dp]);
        }
        __syncthreads();
        float c[2][3][4];
#pragma unroll
        for (int i=0;i<2;i++)
#pragma unroll
        for (int jn=0;jn<3;jn++)
#pragma unroll
        for (int k=0;k<4;k++) c[i][jn][k]=0.f;
#pragma unroll
        for (int kk=0;kk<4;kk++){
            unsigned Ah[2][4], Al[2][4], Bh[3][2], Bl[3][2];
#pragma unroll
            for (int mi=0;mi<2;mi++){
                ldsm4(Ah[mi][0],Ah[mi][1],Ah[mi][2],Ah[mi][3],
                      sAh + (mrow+mi*16)*36 + kk*8 + aoff);
                ldsm4(Al[mi][0],Al[mi][1],Al[mi][2],Al[mi][3],
                      sAl + (mrow+mi*16)*36 + kk*8 + aoff);
            }
            ldsm4(Bh[0][0],Bh[0][1],Bh[1][0],Bh[1][1], sWh2 + ncol*36 + kk*8 + boff);
            ldsm4(Bl[0][0],Bl[0][1],Bl[1][0],Bl[1][1], sWl2 + ncol*36 + kk*8 + boff);
            ldsm2(Bh[2][0],Bh[2][1], sWh2 + (ncol+16)*36 + kk*8 + b2off);
            ldsm2(Bl[2][0],Bl[2][1], sWl2 + (ncol+16)*36 + kk*8 + b2off);
#pragma unroll
            for (int mi=0;mi<2;mi++)
#pragma unroll
            for (int ni=0;ni<3;ni++)
                bmma3(c[mi][ni], Ah[mi], Al[mi], Bh[ni], Bl[ni]);
        }
#pragma unroll
        for (int mi=0;mi<2;mi++){
            int p = mrow+mi*16+gp;
#pragma unroll
            for (int ni=0;ni<3;ni++){
                int n = half*96 + ncol+ni*8+2*tig;
                float bb0 = bias[n], bb1 = bias[n+1];
                *(float2*)(dst + p*192 + n) = make_float2(c[mi][ni][0]+bb0, c[mi][ni][1]+bb1);
                *(float2*)(dst + (p+8)*192 + n) = make_float2(c[mi][ni][2]+bb0, c[mi][ni][3]+bb1);
            }
        }
    }
}

// ---- coarse logits + online stats (r12): grid(32,16) ----
__global__ __launch_bounds__(256) void k_logits_s() {
    int bh = blockIdx.x, qt = blockIdx.y;
    __shared__ unsigned sQh[64*36], sQl[64*36];
    __shared__ unsigned sKh[128*36], sKl[128*36];
    __shared__ float sM[64], sS[64], sRm[256], sRs[256];
    int t=threadIdx.x, w=t>>5, lane=t&31, gp=lane>>2, tig=lane&3;
    int mrow=(w>>2)*32, ncol=(w&3)*32, nw=w&3;
    int aoff = AOFF(lane,36), boff = BOFF(lane,36);
    const float* qkv = g_qkv + (size_t)bh*P*192;
    for (int idx=t; idx<1024; idx+=256){
        int r=idx>>4, f4=idx&15;
        float4 v = *(const float4*)(qkv + (qt*64+r)*192 + f4*4);
        bsplit2(v.x, v.y, sQh[r*36+f4*2],   sQl[r*36+f4*2]);
        bsplit2(v.z, v.w, sQh[r*36+f4*2+1], sQl[r*36+f4*2+1]);
    }
    if (t<64){ sM[t]=-1e30f; sS[t]=0.f; }
    float* dst = g_attn + ((size_t)bh<<20) + (size_t)qt*64*1024;
    for (int s=0; s<8; s++){
        int colbase = s*128;
        __syncthreads();
        for (int idx=t; idx<2048; idx+=256){
            int r=idx>>4, f4=idx&15;
            float4 v = *(const float4*)(qkv + (colbase+r)*192 + 64 + f4*4);
            bsplit2(v.x, v.y, sKh[r*36+f4*2],   sKl[r*36+f4*2]);
            bsplit2(v.z, v.w, sKh[r*36+f4*2+1], sKl[r*36+f4*2+1]);
        }
        __syncthreads();
        float c[2][4][4];
#pragma unroll
        for (int i=0;i<2;i++)
#pragma unroll
        for (int jn=0;jn<4;jn++)
#pragma unroll
        for (int k=0;k<4;k++) c[i][jn][k]=0.f;
#pragma unroll
        for (int kk=0;kk<4;kk++){
            unsigned Ah[2][4], Al[2][4], Bh[4][2], Bl[4][2];
#pragma unroll
            for (int mi=0;mi<2;mi++){
                ldsm4(Ah[mi][0],Ah[mi][1],Ah[mi][2],Ah[mi][3],
                      sQh + (mrow+mi*16)*36 + kk*8 + aoff);
                ldsm4(Al[mi][0],Al[mi][1],Al[mi][2],Al[mi][3],
                      sQl + (mrow+mi*16)*36 + kk*8 + aoff);
            }
            ldsm4(Bh[0][0],Bh[0][1],Bh[1][0],Bh[1][1], sKh + ncol*36 + kk*8 + boff);
            ldsm4(Bl[0][0],Bl[0][1],Bl[1][0],Bl[1][1], sKl + ncol*36 + kk*8 + boff);
            ldsm4(Bh[2][0],Bh[2][1],Bh[3][0],Bh[3][1], sKh + (ncol+16)*36 + kk*8 + boff);
            ldsm4(Bl[2][0],Bl[2][1],Bl[3][0],Bl[3][1], sKl + (ncol+16)*36 + kk*8 + boff);
#pragma unroll
            for (int mi=0;mi<2;mi++)
#pragma unroll
            for (int ni=0;ni<4;ni++)
                bmma3(c[mi][ni], Ah[mi], Al[mi], Bh[ni], Bl[ni]);
        }
#pragma unroll
        for (int i=0;i<2;i++)
#pragma unroll
        for (int jn=0;jn<4;jn++)
#pragma unroll
        for (int k=0;k<4;k++) c[i][jn][k] *= 0.125f;
#pragma unroll
        for (int mi=0;mi<2;mi++)
#pragma unroll
        for (int rh=0;rh<2;rh++){
            float m0 = -1e30f;
#pragma unroll
            for (int ni=0;ni<4;ni++)
                m0 = fmaxf(m0, fmaxf(c[mi][ni][2*rh], c[mi][ni][2*rh+1]));
            m0 = fmaxf(m0, __shfl_xor_sync(0xffffffffu, m0, 1));
            m0 = fmaxf(m0, __shfl_xor_sync(0xffffffffu, m0, 2));
            if (tig==0) sRm[(mrow+mi*16+gp+8*rh)*4 + nw] = m0;
        }
        __syncthreads();
        float mn_[2][2], f_[2][2];
#pragma unroll
        for (int mi=0;mi<2;mi++)
#pragma unroll
        for (int rh=0;rh<2;rh++){
            int r = mrow+mi*16+gp+8*rh;
            float Mc = fmaxf(fmaxf(sRm[r*4],sRm[r*4+1]), fmaxf(sRm[r*4+2],sRm[r*4+3]));
            float mo = sM[r];
            float mnv = fmaxf(mo, Mc);
            mn_[mi][rh] = mnv; f_[mi][rh] = __expf(mo - mnv);
            float s0 = 0.f;
#pragma unroll
            for (int ni=0;ni<4;ni++)
                s0 += __expf(c[mi][ni][2*rh]-mnv) + __expf(c[mi][ni][2*rh+1]-mnv);
            s0 += __shfl_xor_sync(0xffffffffu, s0, 1);
            s0 += __shfl_xor_sync(0xffffffffu, s0, 2);
            if (tig==0) sRs[r*4 + nw] = s0;
        }
        __syncthreads();
        if (nw==0 && tig==0){
#pragma unroll
            for (int mi=0;mi<2;mi++)
#pragma unroll
            for (int rh=0;rh<2;rh++){
                int r = mrow+mi*16+gp+8*rh;
                float Sc = sRs[r*4]+sRs[r*4+1]+sRs[r*4+2]+sRs[r*4+3];
                sS[r] = sS[r]*f_[mi][rh] + Sc;
                sM[r] = mn_[mi][rh];
            }
        }
#pragma unroll
        for (int mi=0;mi<2;mi++)
#pragma unroll
        for (int ni=0;ni<4;ni++){
            int row = mrow+mi*16+gp, col = colbase+ncol+ni*8+2*tig;
            *(float2*)(dst + (size_t)row*1024 + col) = make_float2(c[mi][ni][0], c[mi][ni][1]);
            *(float2*)(dst + (size_t)(row+8)*1024 + col) = make_float2(c[mi][ni][2], c[mi][ni][3]);
        }
    }
    __syncthreads();
    if (nw==0 && tig==0){
#pragma unroll
        for (int mi=0;mi<2;mi++)
#pragma unroll
        for (int rh=0;rh<2;rh++){
            int r = mrow+mi*16+gp+8*rh;
            g_sm[bh*1024 + qt*64 + r] = sM[r];
            g_ssi[bh*1024 + qt*64 + r] = 1.f / sS[r];
        }
    }
}

// ---- coarse attn@V with fused softmax + colsum partials (r12): grid(32,16) ----
__global__ __launch_bounds__(256) void k_av_e() {
    int bh = blockIdx.x, qb = blockIdx.y;
    int b = bh >> 2, h = bh & 3;
    __shared__ unsigned sAh[64*36], sAl[64*36];
    __shared__ unsigned sVh[64*36], sVl[64*36];
    __shared__ float sMv[64], sSv[64], scol[64];
    int t=threadIdx.x, w=t>>5, lane=t&31, gp=lane>>2, tig=lane&3;
    int mrow=(w>>2)*32, ncol=(w&3)*16;
    int aoff = AOFF(lane,36), boff = BOFF(lane,36);
    const float* attn = g_attn + ((size_t)bh << 20) + (size_t)qb*64*1024;
    const float* vptr = g_qkv + (size_t)bh * P * 192 + 128;
    if (t<64){ sMv[t]=g_sm[bh*1024+qb*64+t]; sSv[t]=g_ssi[bh*1024+qb*64+t]; }
    float c[2][2][4];
#pragma unroll
    for (int i=0;i<2;i++)
#pragma unroll
    for (int jn=0;jn<2;jn++)
#pragma unroll
    for (int k=0;k<4;k++) c[i][jn][k]=0.f;
    for (int kc = 0; kc < 16; kc++) {
        __syncthreads();
        if (t<64) scol[t]=0.f;
        __syncthreads();
        float cs0=0.f, cs1=0.f, cs2=0.f, cs3=0.f;
        for (int idx=t; idx<1024; idx+=256){
            int r=idx>>4, f4=idx&15;
            float4 v = *(const float4*)(attn + (size_t)r*1024 + kc*64 + f4*4);
            float mm = sMv[r], is = sSv[r];
            float p0 = __expf(v.x-mm)*is, p1 = __expf(v.y-mm)*is;
            float p2 = __expf(v.z-mm)*is, p3 = __expf(v.w-mm)*is;
            cs0 += p0; cs1 += p1; cs2 += p2; cs3 += p3;
            bsplit2(p0, p1, sAh[r*36+f4*2],   sAl[r*36+f4*2]);
            bsplit2(p2, p3, sAh[r*36+f4*2+1], sAl[r*36+f4*2+1]);
        }
        {
            int f4 = t&15;
            atomicAdd(&scol[f4*4+0], cs0);
            atomicAdd(&scol[f4*4+1], cs1);
            atomicAdd(&scol[f4*4+2], cs2);
            atomicAdd(&scol[f4*4+3], cs3);
        }
        for (int idx=t; idx<2048; idx+=256){
            int d=idx&63, tp=idx>>6;
            float v0 = vptr[(size_t)(kc*64+2*tp)*192 + d];
            float v1 = vptr[(size_t)(kc*64+2*tp+1)*192 + d];
            bsplit2(v0, v1, sVh[d*36+tp], sVl[d*36+tp]);
        }
        __syncthreads();
        if (t<64) g_part[((size_t)bh*16+qb)*1024 + kc*64 + t] = scol[t];
#pragma unroll
        for (int kk=0;kk<4;kk++){
            unsigned Ah[2][4], Al[2][4], Bh[2][2], Bl[2][2];
#pragma unroll
            for (int mi=0;mi<2;mi++){
                ldsm4(Ah[mi][0],Ah[mi][1],Ah[mi][2],Ah[mi][3],
                      sAh + (mrow+mi*16)*36 + kk*8 + aoff);
                ldsm4(Al[mi][0],Al[mi][1],Al[mi][2],Al[mi][3],
                      sAl + (mrow+mi*16)*36 + kk*8 + aoff);
            }
            ldsm4(Bh[0][0],Bh[0][1],Bh[1][0],Bh[1][1], sVh + ncol*36 + kk*8 + boff);
            ldsm4(Bl[0][0],Bl[0][1],Bl[1][0],Bl[1][1], sVl + ncol*36 + kk*8 + boff);
#pragma unroll
            for (int mi=0;mi<2;mi++)
#pragma unroll
            for (int ni=0;ni<2;ni++)
                bmma3(c[mi][ni], Ah[mi], Al[mi], Bh[ni], Bl[ni]);
        }
    }
#pragma unroll
    for (int mi=0;mi<2;mi++)
#pragma unroll
    for (int ni=0;ni<2;ni++){
        int row = qb*64 + mrow+mi*16+gp;
        int d0 = ncol+ni*8+2*tig;
        g_outc[((size_t)(b*C + h*HD + d0  ))*PLANE32 + row] = c[mi][ni][0];
        g_outc[((size_t)(b*C + h*HD + d0+1))*PLANE32 + row] = c[mi][ni][1];
        g_outc[((size_t)(b*C + h*HD + d0  ))*PLANE32 + row + 8] = c[mi][ni][2];
        g_outc[((size_t)(b*C + h*HD + d0+1))*PLANE32 + row + 8] = c[mi][ni][3];
    }
}

// ---- topk: sum partials then bitonic ----
__global__ __launch_bounds__(512) void k_topk() {
    int bh = blockIdx.x;
    __shared__ float sv[1024];
    __shared__ int si[1024];
    int t = threadIdx.x;
    float a0=0.f, a1=0.f;
#pragma unroll
    for (int j=0;j<16;j++){
        a0 += g_part[((size_t)bh*16+j)*1024 + t];
        a1 += g_part[((size_t)bh*16+j)*1024 + t + 512];
    }
    sv[t]=a0; si[t]=t; sv[t+512]=a1; si[t+512]=t+512;
    __syncthreads();
    for (int k = 2; k <= 1024; k <<= 1) {
        for (int j = k >> 1; j > 0; j >>= 1) {
#pragma unroll
            for (int mm = 0; mm < 2; mm++) {
                int i = t + mm*512;
                int l = i ^ j;
                if (l > i) {
                    float vi = sv[i], vl = sv[l];
                    int ii = si[i], il = si[l];
                    bool before = (vi > vl) || (vi == vl && ii < il);
                    bool keep = ((i & k) == 0) ? before : !before;
                    if (!keep) { sv[i] = vl; sv[l] = vi; si[i] = il; si[l] = ii; }
                }
            }
            __syncthreads();
        }
    }
    if (t < 256) g_topk[bh*KF + t] = si[t];
}

// ---- flash attention (fine path), scatter fused into epilogue ----
__global__ __launch_bounds__(256) void k_flash() {
    int bh = blockIdx.x, qt = blockIdx.y;
    __shared__ unsigned sQh[64*36], sQl[64*36];
    __shared__ unsigned sKPh[64*36], sKPl[64*36];
    __shared__ unsigned sVh[64*20], sVl[64*20];
    __shared__ float sM[64], sS[64];
    float* sRm = (float*)sVh;
    float* sRs = (float*)sVl;
    int t=threadIdx.x, w=t>>5, lane=t&31, gp=lane>>2, tig=lane&3;
    int mrow=(w>>2)*32, ncol=(w&3)*16;
    int aoff=AOFF(lane,36), boff=BOFF(lane,36), voff=BOFF(lane,20);
    int nw = w&3;
    const float* qkv = g_qkv + (size_t)bh*P*192;
    for (int idx=t; idx<1024; idx+=256){
        int r=idx>>4, f4=idx&15;
        float4 v = *(const float4*)(qkv + (qt*64+r)*192 + f4*4);
        bsplit2(v.x, v.y, sQh[r*36+f4*2],   sQl[r*36+f4*2]);
        bsplit2(v.z, v.w, sQh[r*36+f4*2+1], sQl[r*36+f4*2+1]);
    }
    if (t < 64){ sM[t] = -1e30f; sS[t] = 0.f; }
    float o[2][2][4];
#pragma unroll
    for (int i=0;i<2;i++)
#pragma unroll
    for (int j=0;j<2;j++)
#pragma unroll
    for (int k=0;k<4;k++) o[i][j][k]=0.f;
    const float* vptr = qkv + 128;
    for (int kc=0; kc<16; kc++){
        __syncthreads();
        for (int idx=t; idx<1024; idx+=256){
            int r=idx>>4, f4=idx&15;
            float4 v = *(const float4*)(qkv + (kc*64+r)*192 + 64 + f4*4);
            bsplit2(v.x, v.y, sKPh[r*36+f4*2],   sKPl[r*36+f4*2]);
            bsplit2(v.z, v.w, sKPh[r*36+f4*2+1], sKPl[r*36+f4*2+1]);
        }
        __syncthreads();
        float c[2][2][4];
#pragma unroll
        for (int i=0;i<2;i++)
#pragma unroll
        for (int j=0;j<2;j++)
#pragma unroll
        for (int k=0;k<4;k++) c[i][j][k]=0.f;
#pragma unroll
        for (int kk=0;kk<4;kk++){
            unsigned Ah[2][4], Al[2][4], Bh[2][2], Bl[2][2];
#pragma unroll
            for (int mi=0;mi<2;mi++){
                ldsm4(Ah[mi][0],Ah[mi][1],Ah[mi][2],Ah[mi][3],
                      sQh + (mrow+mi*16)*36 + kk*8 + aoff);
                ldsm4(Al[mi][0],Al[mi][1],Al[mi][2],Al[mi][3],
                      sQl + (mrow+mi*16)*36 + kk*8 + aoff);
            }
            ldsm4(Bh[0][0],Bh[0][1],Bh[1][0],Bh[1][1], sKPh + ncol*36 + kk*8 + boff);
            ldsm4(Bl[0][0],Bl[0][1],Bl[1][0],Bl[1][1], sKPl + ncol*36 + kk*8 + boff);
#pragma unroll
            for (int mi=0;mi<2;mi++)
#pragma unroll
            for (int ni=0;ni<2;ni++)
                bmma3(c[mi][ni], Ah[mi], Al[mi], Bh[ni], Bl[ni]);
        }
#pragma unroll
        for (int i=0;i<2;i++)
#pragma unroll
        for (int j=0;j<2;j++)
#pragma unroll
        for (int k=0;k<4;k++) c[i][j][k] *= 0.125f;
#pragma unroll
        for (int mi=0;mi<2;mi++)
#pragma unroll
        for (int rh=0;rh<2;rh++){
            float m0 = fmaxf(fmaxf(c[mi][0][2*rh], c[mi][0][2*rh+1]),
                             fmaxf(c[mi][1][2*rh], c[mi][1][2*rh+1]));
            m0 = fmaxf(m0, __shfl_xor_sync(0xffffffffu, m0, 1));
            m0 = fmaxf(m0, __shfl_xor_sync(0xffffffffu, m0, 2));
            if (tig==0) sRm[(mrow+mi*16+gp+8*rh)*4 + nw] = m0;
        }
        __syncthreads();
        float f_[2][2], mn_[2][2];
#pragma unroll
        for (int mi=0;mi<2;mi++)
#pragma unroll
        for (int rh=0;rh<2;rh++){
            int r = mrow+mi*16+gp+8*rh;
            float Mc = fmaxf(fmaxf(sRm[r*4+0], sRm[r*4+1]), fmaxf(sRm[r*4+2], sRm[r*4+3]));
            float mo = sM[r];
            float mnv = fmaxf(mo, Mc);
            mn_[mi][rh] = mnv;
            f_[mi][rh] = __expf(mo - mnv);
        }
#pragma unroll
        for (int mi=0;mi<2;mi++)
#pragma unroll
        for (int ni=0;ni<2;ni++)
#pragma unroll
        for (int k=0;k<4;k++)
            c[mi][ni][k] = __expf(c[mi][ni][k] - mn_[mi][k>>1]);
#pragma unroll
        for (int mi=0;mi<2;mi++)
#pragma unroll
        for (int rh=0;rh<2;rh++){
            float s0 = c[mi][0][2*rh] + c[mi][0][2*rh+1] + c[mi][1][2*rh] + c[mi][1][2*rh+1];
            s0 += __shfl_xor_sync(0xffffffffu, s0, 1);
            s0 += __shfl_xor_sync(0xffffffffu, s0, 2);
            if (tig==0) sRs[(mrow+mi*16+gp+8*rh)*4 + nw] = s0;
        }
        __syncthreads();
#pragma unroll
        for (int mi=0;mi<2;mi++)
#pragma unroll
        for (int ni=0;ni<2;ni++)
#pragma unroll
        for (int k=0;k<4;k++) o[mi][ni][k] *= f_[mi][k>>1];
        if (nw==0 && tig==0){
#pragma unroll
            for (int mi=0;mi<2;mi++)
#pragma unroll
            for (int rh=0;rh<2;rh++){
                int r = mrow+mi*16+gp+8*rh;
                float Sc = sRs[r*4+0]+sRs[r*4+1]+sRs[r*4+2]+sRs[r*4+3];
                sS[r] = sS[r]*f_[mi][rh] + Sc;
                sM[r] = mn_[mi][rh];
            }
        }
#pragma unroll
        for (int mi=0;mi<2;mi++){
            int r0 = mrow+mi*16+gp;
#pragma unroll
            for (int ni=0;ni<2;ni++){
                int p2 = nw*8 + ni*4 + tig;
                bsplit2(c[mi][ni][0], c[mi][ni][1], sKPh[r0*36 + p2],     sKPl[r0*36 + p2]);
                bsplit2(c[mi][ni][2], c[mi][ni][3], sKPh[(r0+8)*36 + p2], sKPl[(r0+8)*36 + p2]);
            }
        }
#pragma unroll
        for (int vh=0; vh<2; vh++){
            __syncthreads();
            for (int idx=t; idx<1024; idx+=256){
                int d=idx&63, tp=idx>>6;
                float v0 = vptr[(size_t)(kc*64+vh*32+2*tp)*192 + d];
                float v1 = vptr[(size_t)(kc*64+vh*32+2*tp+1)*192 + d];
                bsplit2(v0, v1, sVh[d*20+tp], sVl[d*20+tp]);
            }
            __syncthreads();
#pragma unroll
            for (int kl=0;kl<2;kl++){
                unsigned Ah[2][4], Al[2][4], Bh[2][2], Bl[2][2];
                int kk = vh*2 + kl;
#pragma unroll
                for (int mi=0;mi<2;mi++){
                    ldsm4(Ah[mi][0],Ah[mi][1],Ah[mi][2],Ah[mi][3],
                          sKPh + (mrow+mi*16)*36 + kk*8 + aoff);
                    ldsm4(Al[mi][0],Al[mi][1],Al[mi][2],Al[mi][3],
                          sKPl + (mrow+mi*16)*36 + kk*8 + aoff);
                }
                ldsm4(Bh[0][0],Bh[0][1],Bh[1][0],Bh[1][1], sVh + ncol*20 + kl*8 + voff);
                ldsm4(Bl[0][0],Bl[0][1],Bl[1][0],Bl[1][1], sVl + ncol*20 + kl*8 + voff);
#pragma unroll
                for (int mi=0;mi<2;mi++)
#pragma unroll
                for (int ni=0;ni<2;ni++)
                    bmma3(o[mi][ni], Ah[mi], Al[mi], Bh[ni], Bl[ni]);
            }
        }
    }
    __syncthreads();
    {
        int b = bh>>2, h = bh&3;
#pragma unroll
        for (int mi=0;mi<2;mi++){
            float inv0 = 1.f / sS[mrow+mi*16+gp];
            float inv1 = 1.f / sS[mrow+mi*16+gp+8];
            int tok0 = qt*64 + mrow+mi*16+gp;
            int tok1 = tok0 + 8;
            int p0 = g_topk[bh*KF + (tok0>>2)], s0i = tok0&3;
            int p1 = g_topk[bh*KF + (tok1>>2)], s1i = tok1&3;
            int yy0 = ((p0>>5)<<1)+(s0i>>1), xx0 = ((p0&31)<<1)+(s0i&1);
            int yy1 = ((p1>>5)<<1)+(s1i>>1), xx1 = ((p1&31)<<1)+(s1i&1);
            size_t base0 = (((size_t)(b*C + h*HD))<<12) + (yy0<<6) + xx0;
            size_t base1 = (((size_t)(b*C + h*HD))<<12) + (yy1<<6) + xx1;
#pragma unroll
            for (int ni=0;ni<2;ni++){
                int d0 = ncol+ni*8+2*tig;
                g_y[base0 + ((size_t)d0<<12)]     += o[mi][ni][0]*inv0;
                g_y[base0 + ((size_t)(d0+1)<<12)] += o[mi][ni][1]*inv0;
                g_y[base1 + ((size_t)d0<<12)]     += o[mi][ni][2]*inv1;
                g_y[base1 + ((size_t)(d0+1)<<12)] += o[mi][ni][3]*inv1;
            }
        }
    }
}

// ---- depthwise 3x3 + BN + relu6, 2 channels/block, packed bf16 out: grid(1024) ----
__global__ __launch_bounds__(256) void k_dw(const float* __restrict__ wdw,
                                            const float* __restrict__ g,
                                            const float* __restrict__ bb,
                                            const float* __restrict__ m,
                                            const float* __restrict__ vv) {
    int bc2 = blockIdx.x;                 // b*128 + cpair
    __shared__ float sp0[66*66], sp1[66*66];
    int t = threadIdx.x;
    int c0 = 2*(bc2 & 127);
    const float* p0 = g_y + ((size_t)bc2 << 13);
    const float* p1 = p0 + 4096;
    for (int idx=t; idx<4356; idx+=256){
        int r = idx/66, cx = idx - r*66;
        int iy = r-1, ix = cx-1;
        bool in = (iy>=0 && iy<64 && ix>=0 && ix<64);
        int src = (iy<<6)+ix;
        sp0[idx] = in ? p0[src] : 0.f;
        sp1[idx] = in ? p1[src] : 0.f;
    }
    __syncthreads();
    const float* wc0 = wdw + c0*9;
    const float* wc1 = wdw + (c0+1)*9;
    float sc0 = g[c0] * rsqrtf(vv[c0] + 1e-5f);
    float of0 = bb[c0] - m[c0] * sc0;
    float sc1 = g[c0+1] * rsqrtf(vv[c0+1] + 1e-5f);
    float of1 = bb[c0+1] - m[c0+1] * sc1;
#pragma unroll
    for (int i=0;i<16;i++){
        int p = t + i*256;
        int y = p>>6, x = p&63;
        const float* s0 = sp0 + y*66 + x;
        const float* s1 = sp1 + y*66 + x;
        float a0 = wc0[0]*s0[0] + wc0[1]*s0[1] + wc0[2]*s0[2]
                 + wc0[3]*s0[66] + wc0[4]*s0[67] + wc0[5]*s0[68]
                 + wc0[6]*s0[132] + wc0[7]*s0[133] + wc0[8]*s0[134];
        float a1 = wc1[0]*s1[0] + wc1[1]*s1[1] + wc1[2]*s1[2]
                 + wc1[3]*s1[66] + wc1[4]*s1[67] + wc1[5]*s1[68]
                 + wc1[6]*s1[132] + wc1[7]*s1[133] + wc1[8]*s1[134];
        float r0 = fminf(fmaxf(a0*sc0 + of0, 0.f), 6.f);
        float r1 = fminf(fmaxf(a1*sc1 + of1, 0.f), 6.f);
        size_t o = ((size_t)bc2 << 12) + p;
        bsplit2(r0, r1, g_ydh[o], g_ydl[o]);
    }
}

// ---- pointwise bf16: grid(8,32,4), packed X staging ----
__global__ __launch_bounds__(256) void k_pw_t(const float* __restrict__ g,
                                              const float* __restrict__ bb,
                                              const float* __restrict__ m,
                                              const float* __restrict__ vv,
                                              float* __restrict__ out) {
    int b = blockIdx.x, sp = blockIdx.y, cg = blockIdx.z;
    __shared__ unsigned sWh[64*20], sWl[64*20];
    __shared__ unsigned sXh[128*20], sXl[128*20];
    int t=threadIdx.x, w=t>>5, lane=t&31, gp=lane>>2, tig=lane&3;
    int mrow=(w>>2)*32, ncol=(w&3)*32;
    int aoff = AOFF(lane,20), boff = BOFF(lane,20);
    float c[2][4][4];
#pragma unroll
    for (int i=0;i<2;i++)
#pragma unroll
    for (int jn=0;jn<4;jn++)
#pragma unroll
    for (int k=0;k<4;k++) c[i][jn][k]=0.f;
    for (int cc = 0; cc < 8; cc++) {
        __syncthreads();
        {
            int idx = t;
            int co=idx>>2, c4=(idx&3)<<2;
            *(uint4*)(sWh + co*20 + c4) = *(const uint4*)(g_pwh + (size_t)(cg*64+co)*128 + cc*16 + c4);
            *(uint4*)(sWl + co*20 + c4) = *(const uint4*)(g_pwl + (size_t)(cg*64+co)*128 + cc*16 + c4);
        }
        for (int idx=t; idx<2048; idx+=256){
            int px = idx&127, kp = idx>>7;
            size_t src = ((size_t)(b*128 + cc*16 + kp) << 12) + sp*128 + px;
            sXh[px*20+kp] = g_ydh[src];
            sXl[px*20+kp] = g_ydl[src];
        }
        __syncthreads();
#pragma unroll
        for (int kk=0;kk<2;kk++){
            unsigned Ah[2][4], Al[2][4], Bh[4][2], Bl[4][2];
#pragma unroll
            for (int mi=0;mi<2;mi++){
                ldsm4(Ah[mi][0],Ah[mi][1],Ah[mi][2],Ah[mi][3],
                      sWh + (mrow+mi*16)*20 + kk*8 + aoff);
                ldsm4(Al[mi][0],Al[mi][1],Al[mi][2],Al[mi][3],
                      sWl + (mrow+mi*16)*20 + kk*8 + aoff);
            }
            ldsm4(Bh[0][0],Bh[0][1],Bh[1][0],Bh[1][1], sXh + ncol*20 + kk*8 + boff);
            ldsm4(Bl[0][0],Bl[0][1],Bl[1][0],Bl[1][1], sXl + ncol*20 + kk*8 + boff);
            ldsm4(Bh[2][0],Bh[2][1],Bh[3][0],Bh[3][1], sXh + (ncol+16)*20 + kk*8 + boff);
            ldsm4(Bl[2][0],Bl[2][1],Bl[3][0],Bl[3][1], sXl + (ncol+16)*20 + kk*8 + boff);
#pragma unroll
            for (int mi=0;mi<2;mi++)
#pragma unroll
            for (int ni=0;ni<4;ni++)
                bmma3(c[mi][ni], Ah[mi], Al[mi], Bh[ni], Bl[ni]);
        }
    }
#pragma unroll
    for (int mi=0;mi<2;mi++){
        int co = cg*64 + mrow+mi*16+gp;
        float sc0 = g[co] * rsqrtf(vv[co] + 1e-5f);
        float of0 = bb[co] - m[co] * sc0;
        float sc1 = g[co+8] * rsqrtf(vv[co+8] + 1e-5f);
        float of1 = bb[co+8] - m[co+8] * sc1;
#pragma unroll
        for (int ni=0;ni<4;ni++){
            int px = sp*128 + ncol+ni*8+2*tig;
            float r0 = fminf(fmaxf(c[mi][ni][0]*sc0 + of0, 0.f), 6.f);
            float r1 = fminf(fmaxf(c[mi][ni][1]*sc0 + of0, 0.f), 6.f);
            float r2 = fminf(fmaxf(c[mi][ni][2]*sc1 + of1, 0.f), 6.f);
            float r3 = fminf(fmaxf(c[mi][ni][3]*sc1 + of1, 0.f), 6.f);
            *(float2*)(out + ((size_t)(b*C+co))*HW + px)   = make_float2(r0, r1);
            *(float2*)(out + ((size_t)(b*C+co+8))*HW + px) = make_float2(r2, r3);
        }
    }
}

extern "C" void kernel_launch(void* const* d_in, const int* in_sizes, int n_in,
                              void* d_out, int out_size) {
    const float* x       = (const float*)d_in[0];
    const float* w_down  = (const float*)d_in[1];
    const float* b_down  = (const float*)d_in[2];
    const float* w_qkv_c = (const float*)d_in[3];
    const float* b_qkv_c = (const float*)d_in[4];
    const float* w_up    = (const float*)d_in[5];
    const float* b_up    = (const float*)d_in[6];
    const float* w_qkv_f = (const float*)d_in[7];
    const float* b_qkv_f = (const float*)d_in[8];
    const float* w_dw    = (const float*)d_in[9];
    const float* bn_dw_g = (const float*)d_in[10];
    const float* bn_dw_b = (const float*)d_in[11];
    const float* bn_dw_m = (const float*)d_in[12];
    const float* bn_dw_v = (const float*)d_in[13];
    const float* w_pw    = (const float*)d_in[14];
    const float* bn_pw_g = (const float*)d_in[15];
    const float* bn_pw_b = (const float*)d_in[16];
    const float* bn_pw_m = (const float*)d_in[17];
    const float* bn_pw_v = (const float*)d_in[18];
    float* out = (float*)d_out;

    k_prep_wd<<<2048, 256>>>(w_down);
    k_wt<<<2048, 256>>>(w_up);
    k_prep_pw<<<128, 256>>>(w_pw);

    // ---- coarse path (r12 structure) ----
    k_down_t<<<dim3(128, 4), 256>>>(x, b_down);
    k_qkv_t<<<dim3(32, 16), 256>>>(w_qkv_c, b_qkv_c, 0);
    k_logits_s<<<dim3(32, 16), 256>>>();
    k_av_e<<<dim3(32, 16), 256>>>();
    k_topk<<<32, 512>>>();
    k_up_t<<<dim3(64, 16), 256>>>(b_up);

    // ---- fine path (flash-fused, scatter in epilogue) ----
    k_qkv_t<<<dim3(32, 16), 256>>>(w_qkv_f, b_qkv_f, 1);
    k_flash<<<dim3(32, 16), 256>>>();

    // ---- feed-forward ----
    k_dw<<<1024, 256>>>(w_dw, bn_dw_g, bn_dw_b, bn_dw_m, bn_dw_v);
    k_pw_t<<<dim3(8, 32, 4), 256>>>(bn_pw_g, bn_pw_b, bn_pw_m, bn_pw_v, out);
}